// round 14
// baseline (speedup 1.0000x reference)
#include <cuda_runtime.h>
#include <cuda_bf16.h>
#include <math.h>
#include <stdint.h>

#define BB 64
#define CC 768
#define LL 197
#define NBL (BB*LL)
#define EPSV 1e-5f
#define MDIM 2304
#define KDIM 6912
#define KCH  2304
#define NROW 200
#define NP   (BB*NROW)
#define NZROWS (NP+4)
#define NCHUNK 216
#define RSTRIDE 80
// conv: 128x320 tile, 3-stage
#define NT 320
#define A_BYTES (128*RSTRIDE)          // 10240 per array
#define B_BYTES (NT*RSTRIDE)           // 25600 per array
#define STG_BYTES (2*A_BYTES + 2*B_BYTES)   // 71680
#define SMEMSZ (3*STG_BYTES)                // 215040
// attention
#define LPAD 256
#define JPAD 224
#define ABT (128*RSTRIDE)
#define TSTG (4*128*RSTRIDE)
#define TSMEM (3*TSTG)

__device__ __nv_bfloat16 g_zhi[(size_t)NZROWS * KCH];
__device__ __nv_bfloat16 g_zlo[(size_t)NZROWS * KCH];
__device__ __nv_bfloat16 g_whi[(size_t)MDIM * KDIM];
__device__ __nv_bfloat16 g_wlo[(size_t)MDIM * KDIM];
__device__ float g_bias[3][MDIM];
__device__ float g_q[(size_t)BB * CC * LL];
__device__ float g_k[(size_t)BB * CC * LL];
__device__ float g_v[(size_t)BB * CC * LL];
__device__ __nv_bfloat16 g_Qh[(size_t)BB * LPAD * CC];
__device__ __nv_bfloat16 g_Ql[(size_t)BB * LPAD * CC];
__device__ __nv_bfloat16 g_Kh[(size_t)BB * LPAD * CC];
__device__ __nv_bfloat16 g_Kl[(size_t)BB * LPAD * CC];
__device__ float g_att[(size_t)BB * LL * LL];
__device__ __nv_bfloat16 g_atth[(size_t)BB * LPAD * JPAD];
__device__ __nv_bfloat16 g_attl[(size_t)BB * LPAD * JPAD];
__device__ __nv_bfloat16 g_vh[(size_t)BB * CC * JPAD];
__device__ __nv_bfloat16 g_vl[(size_t)BB * CC * JPAD];
__device__ float g_y[(size_t)BB * CC * LL];
__device__ float g_coeff[4 * CC];
__device__ float g_off[4 * CC];

__device__ __forceinline__ uint32_t s2u(const void* p) {
    uint32_t a;
    asm("{ .reg .u64 t; cvta.to.shared.u64 t, %1; cvt.u32.u64 %0, t; }" : "=r"(a) : "l"(p));
    return a;
}
#define CPA16(dst, src) \
    asm volatile("cp.async.cg.shared.global [%0], [%1], 16;" :: "r"(dst), "l"(src) : "memory")
__device__ __forceinline__ void ldsm4(uint32_t* r, uint32_t addr) {
    asm volatile("ldmatrix.sync.aligned.m8n8.x4.shared.b16 {%0,%1,%2,%3}, [%4];"
                 : "=r"(r[0]), "=r"(r[1]), "=r"(r[2]), "=r"(r[3]) : "r"(addr));
}
__device__ __forceinline__ void mma16816(float* c, const uint32_t* a, const uint32_t* b) {
    asm volatile(
        "mma.sync.aligned.m16n8k16.row.col.f32.bf16.bf16.f32 "
        "{%0,%1,%2,%3}, {%4,%5,%6,%7}, {%8,%9}, {%0,%1,%2,%3};"
        : "+f"(c[0]), "+f"(c[1]), "+f"(c[2]), "+f"(c[3])
        : "r"(a[0]), "r"(a[1]), "r"(a[2]), "r"(a[3]), "r"(b[0]), "r"(b[1]));
}
__device__ __forceinline__ void bf16split(float v, __nv_bfloat16* hi, __nv_bfloat16* lo) {
    __nv_bfloat16 h = __float2bfloat16(v);
    *hi = h;
    *lo = __float2bfloat16(v - __bfloat162float(h));
}

// ---- build_zT with pad-zeroing merged ----
#define ZT_MAIN (BB*CC*LL)
#define ZT_PADS (196*KCH)
__global__ void build_zT(const float* __restrict__ x) {
    int idx = blockIdx.x * blockDim.x + threadIdx.x;
    if (idx < ZT_MAIN) {
        int l = idx % LL;
        int bc = idx / LL;
        int c = bc % CC, b = bc / CC;
        float t = tanhf(x[idx]);
        float T[3];
        T[0] = t; T[1] = 2.f * t * t - 1.f; T[2] = 2.f * t * T[1] - t;
        size_t base = ((size_t)(b * NROW + l + 1)) * KCH + c * 3;
        #pragma unroll
        for (int d = 0; d < 3; d++)
            bf16split(T[d], &g_zhi[base + d], &g_zlo[base + d]);
    } else if (idx < ZT_MAIN + ZT_PADS) {
        int p = idx - ZT_MAIN;
        int rid = p / KCH, c = p - rid * KCH;
        int row;
        if (rid < 192) {
            int b = rid / 3, s = rid % 3;
            row = b * NROW + (s == 0 ? 0 : (s == 1 ? 198 : 199));
        } else row = NP + (rid - 192);
        size_t o = (size_t)row * KCH + c;
        g_zhi[o] = __float2bfloat16(0.f);
        g_zlo[o] = __float2bfloat16(0.f);
    }
}

__global__ void build_W_all(const float* __restrict__ Wq, const float* __restrict__ Wk,
                            const float* __restrict__ Wv) {
    int idx = blockIdx.x * blockDim.x + threadIdx.x;
    if (idx >= MDIM * KDIM) return;
    int k = idx % KDIM;
    int gm = idx / KDIM;
    int which = gm / CC, co = gm - which * CC;
    const float* W = (which == 0) ? Wq : (which == 1) ? Wk : Wv;
    int tap = k / KCH, rem = k - tap * KCH;
    int ci = rem / 3, d = rem - ci * 3 + 1;
    float v = W[(size_t)co * (3072 * 3) + (size_t)(ci * 4 + d) * 3 + tap];
    size_t o = (size_t)gm * KDIM + k;
    bf16split(v, &g_whi[o], &g_wlo[o]);
}

__global__ void build_bias(const float* __restrict__ Wq, const float* __restrict__ Wk,
                           const float* __restrict__ Wv) {
    int gm = blockIdx.x;
    int which = gm / CC, co = gm - which * CC;
    const float* W = (which == 0) ? Wq : (which == 1) ? Wk : Wv;
    int tap = threadIdx.x >> 5, lane = threadIdx.x & 31;
    float s = 0.f;
    for (int ci = lane; ci < CC; ci += 32)
        s += W[(size_t)co * (3072 * 3) + (size_t)(ci * 4) * 3 + tap];
    #pragma unroll
    for (int o = 16; o; o >>= 1) s += __shfl_xor_sync(0xffffffffu, s, o);
    if (lane == 0) g_bias[tap][gm] = s;
}

// bf16x3 conv-GEMM, 512 threads, 128x320 tile, warp grid 4(M32)x4(N80), 3-stage
__global__ void __launch_bounds__(512, 1)
conv_mma() {
    extern __shared__ char smem[];
    uint32_t sb = s2u(smem);
    int tid = threadIdx.x, wid = tid >> 5, lane = tid & 31;
    int m0 = blockIdx.x * 128, n0 = blockIdx.y * NT;
    int which = m0 / CC, co0 = m0 - which * CC;
    int wm = wid & 3;       // 4 warp rows (32 M each)
    int wn = wid >> 2;      // 4 warp cols (80 N each)

    float acc[2][10][4];
    #pragma unroll
    for (int mt = 0; mt < 2; mt++)
        #pragma unroll
        for (int nt = 0; nt < 10; nt++)
            #pragma unroll
            for (int e = 0; e < 4; e++) acc[mt][nt][e] = 0.f;

    auto load_chunk = [&](int c, int s) {
        int tap = c / 72;
        int koff = (c - tap * 72) * 32;
        uint32_t st = sb + s * STG_BYTES;
        size_t kb = (size_t)tap * KCH + koff;
        // A: 128 rows x 4 j x 2 arr = 1024 cp16 -> 2/thread
        #pragma unroll
        for (int i = 0; i < 2; i++) {
            int idx = tid + 512 * i;
            int row = idx >> 3, sub = idx & 7;
            int arr = sub >> 2, j = sub & 3;
            const __nv_bfloat16* src =
                (arr ? g_wlo : g_whi) + (size_t)(m0 + row) * KDIM + kb + j * 8;
            CPA16(st + arr * A_BYTES + row * RSTRIDE + j * 16, src);
        }
        // B: 320 rows x 4 x 2 = 2560 cp16 -> 5/thread
        #pragma unroll
        for (int i = 0; i < 5; i++) {
            int idx = tid + 512 * i;
            int row = idx >> 3, sub = idx & 7;
            int arr = sub >> 2, j = sub & 3;
            const __nv_bfloat16* src =
                (arr ? g_zlo : g_zhi) + (size_t)(n0 + row + tap) * KCH + koff + j * 8;
            CPA16(st + 2 * A_BYTES + arr * B_BYTES + row * RSTRIDE + j * 16, src);
        }
    };

    load_chunk(0, 0);
    asm volatile("cp.async.commit_group;" ::: "memory");
    load_chunk(1, 1);
    asm volatile("cp.async.commit_group;" ::: "memory");

    int g = lane >> 3, r = lane & 7;

    for (int c = 0; c < NCHUNK; c++) {
        int s = c % 3;
        asm volatile("cp.async.wait_group 1;" ::: "memory");
        __syncthreads();
        uint32_t stg = sb + s * STG_BYTES;
        #pragma unroll
        for (int ks = 0; ks < 2; ks++) {
            uint32_t ah[2][4], al[2][4];
            #pragma unroll
            for (int mt = 0; mt < 2; mt++) {
                uint32_t arow = (uint32_t)(wm * 32 + mt * 16 + r + (g & 1) * 8);
                uint32_t acol = (uint32_t)((2 * ks + (g >> 1)) * 16);
                ldsm4(ah[mt], stg + arow * RSTRIDE + acol);
                ldsm4(al[mt], stg + A_BYTES + arow * RSTRIDE + acol);
            }
            #pragma unroll
            for (int np = 0; np < 5; np++) {
                uint32_t brow = (uint32_t)(wn * 80 + np * 16 + (g >> 1) * 8 + r);
                uint32_t bcol = (uint32_t)((2 * ks + (g & 1)) * 16);
                uint32_t bh[4], bl[4];
                ldsm4(bh, stg + 2 * A_BYTES + brow * RSTRIDE + bcol);
                ldsm4(bl, stg + 2 * A_BYTES + B_BYTES + brow * RSTRIDE + bcol);
                #pragma unroll
                for (int mt = 0; mt < 2; mt++) {
                    mma16816(acc[mt][2 * np],     ah[mt], &bh[0]);
                    mma16816(acc[mt][2 * np + 1], ah[mt], &bh[2]);
                    mma16816(acc[mt][2 * np],     ah[mt], &bl[0]);
                    mma16816(acc[mt][2 * np + 1], ah[mt], &bl[2]);
                    mma16816(acc[mt][2 * np],     al[mt], &bh[0]);
                    mma16816(acc[mt][2 * np + 1], al[mt], &bh[2]);
                }
            }
        }
        if (c + 2 < NCHUNK) load_chunk(c + 2, (c + 2) % 3);
        asm volatile("cp.async.commit_group;" ::: "memory");
    }

    float* outp = (which == 0) ? g_q : (which == 1) ? g_k : g_v;
    int lrow = lane >> 2, lcol = (lane & 3) * 2;
    #pragma unroll
    for (int mt = 0; mt < 2; mt++) {
        int m_lo = wm * 32 + mt * 16 + lrow;
        float b0[2], b1[2], b2[2];
        #pragma unroll
        for (int h = 0; h < 2; h++) {
            int gm = m0 + m_lo + h * 8;
            b0[h] = g_bias[0][gm]; b1[h] = g_bias[1][gm]; b2[h] = g_bias[2][gm];
        }
        #pragma unroll
        for (int nt = 0; nt < 10; nt++) {
            int ncol = n0 + wn * 80 + nt * 8 + lcol;
            #pragma unroll
            for (int e = 0; e < 4; e++) {
                int h = e >> 1;
                int m = m_lo + h * 8;
                int n = ncol + (e & 1);
                int b = n / NROW;
                int l = n - b * NROW;
                if (l < LL) {
                    float bias = b0[h] + b1[h] + b2[h];
                    if (l == 0)   bias -= b0[h];
                    if (l == 196) bias -= b2[h];
                    outp[((size_t)b * CC + (co0 + m)) * LL + l] = acc[mt][nt][e] + bias;
                }
            }
        }
    }
}

__global__ void bn_stats3(const float* __restrict__ sq, const float* __restrict__ bq,
                          const float* __restrict__ sk, const float* __restrict__ bk,
                          const float* __restrict__ sv, const float* __restrict__ bv) {
    int sel = blockIdx.y;
    const float* in = (sel == 0) ? g_q : (sel == 1) ? g_k : g_v;
    const float* scale = (sel == 0) ? sq : (sel == 1) ? sk : sv;
    const float* bias  = (sel == 0) ? bq : (sel == 1) ? bk : bv;
    int c = blockIdx.x;
    float s = 0.f, s2 = 0.f;
    for (int i = threadIdx.x; i < NBL; i += 256) {
        int b = i / LL, l = i - b * LL;
        float v = in[((size_t)b * CC + c) * LL + l];
        s += v; s2 += v * v;
    }
    __shared__ float sh[256], sh2[256];
    sh[threadIdx.x] = s; sh2[threadIdx.x] = s2;
    __syncthreads();
    for (int st = 128; st > 0; st >>= 1) {
        if (threadIdx.x < st) { sh[threadIdx.x] += sh[threadIdx.x + st]; sh2[threadIdx.x] += sh2[threadIdx.x + st]; }
        __syncthreads();
    }
    if (threadIdx.x == 0) {
        float m = sh[0] / (float)NBL;
        float var = sh2[0] / (float)NBL - m * m;
        float cf = scale[c] * rsqrtf(var + EPSV);
        g_coeff[sel * CC + c] = cf;
        g_off[sel * CC + c]   = bias[c] - m * cf;
    }
}

__global__ void bn_stats(int sel, const float* __restrict__ scale, const float* __restrict__ bias) {
    int c = blockIdx.x;
    float s = 0.f, s2 = 0.f;
    for (int i = threadIdx.x; i < NBL; i += 256) {
        int b = i / LL, l = i - b * LL;
        float v = g_y[((size_t)b * CC + c) * LL + l];
        s += v; s2 += v * v;
    }
    __shared__ float sh[256], sh2[256];
    sh[threadIdx.x] = s; sh2[threadIdx.x] = s2;
    __syncthreads();
    for (int st = 128; st > 0; st >>= 1) {
        if (threadIdx.x < st) { sh[threadIdx.x] += sh[threadIdx.x + st]; sh2[threadIdx.x] += sh2[threadIdx.x + st]; }
        __syncthreads();
    }
    if (threadIdx.x == 0) {
        float m = sh[0] / (float)NBL;
        float var = sh2[0] / (float)NBL - m * m;
        float cf = scale[c] * rsqrtf(var + EPSV);
        g_coeff[sel * CC + c] = cf;
        g_off[sel * CC + c]   = bias[c] - m * cf;
    }
}

__global__ void rope_kernel(const float* __restrict__ freqs) {
    int b  = blockIdx.z;
    int c0 = blockIdx.y * 64;
    int l0 = blockIdx.x * 32;
    __shared__ float s[64][33];
    for (int which = 0; which < 2; which++) {
        const float* src = which ? g_k : g_q;
        const float* cf  = g_coeff + which * CC;
        const float* of  = g_off   + which * CC;
        __nv_bfloat16* dh = which ? g_Kh : g_Qh;
        __nv_bfloat16* dl = which ? g_Kl : g_Ql;
        for (int t = threadIdx.x; t < 64 * 32; t += 256) {
            int cl = t / 32, ll = t - cl * 32;
            int c = c0 + cl, l = l0 + ll;
            float v = 0.f;
            if (l < LL) v = src[((size_t)b * CC + c) * LL + l] * cf[c] + of[c];
            s[cl][ll] = v;
        }
        __syncthreads();
        for (int t = threadIdx.x; t < 32 * 32; t += 256) {
            int ll = t / 32, dl2 = t - ll * 32;
            int l = l0 + ll;
            if (l < LL) {
                int d = c0 / 2 + dl2;
                float a  = s[2 * dl2][ll];
                float bb = s[2 * dl2 + 1][ll];
                float ra, rb;
                if (l == 0) { ra = a; rb = bb; }
                else {
                    float nf = (float)(l - 1);
                    float tx = fmodf(nf, 14.0f);
                    float ty = floorf(nf / 14.0f);
                    float ang = tx * freqs[d] + ty * freqs[384 + d];
                    float sn, cs;
                    sincosf(ang, &sn, &cs);
                    ra = a * cs - bb * sn;
                    rb = a * sn + bb * cs;
                }
                size_t o = ((size_t)b * LPAD + l) * CC + c0 + 2 * dl2;
                bf16split(ra, &dh[o], &dl[o]);
                bf16split(rb, &dh[o + 1], &dl[o + 1]);
            }
        }
        __syncthreads();
    }
}

__global__ void __launch_bounds__(256)
energy_mma() {
    extern __shared__ char smem[];
    uint32_t sb = s2u(smem);
    int tid = threadIdx.x, wid = tid >> 5, lane = tid & 31;
    int m0 = blockIdx.x * 128, n0 = blockIdx.y * 128, b = blockIdx.z;
    int wm = wid & 1, wn = wid >> 1;
    const __nv_bfloat16* Ah = g_Qh + (size_t)b * LPAD * CC;
    const __nv_bfloat16* Al = g_Ql + (size_t)b * LPAD * CC;
    const __nv_bfloat16* Bh = g_Kh + (size_t)b * LPAD * CC;
    const __nv_bfloat16* Bl = g_Kl + (size_t)b * LPAD * CC;

    float acc[4][4][4];
    #pragma unroll
    for (int mt = 0; mt < 4; mt++)
        #pragma unroll
        for (int nt = 0; nt < 4; nt++)
            #pragma unroll
            for (int e = 0; e < 4; e++) acc[mt][nt][e] = 0.f;

    auto load_chunk = [&](int c, int s) {
        int k0 = c * 32;
        uint32_t st = sb + s * TSTG;
        #pragma unroll
        for (int i = 0; i < 2; i++) {
            int idx = tid + 256 * i;
            int row = idx >> 2, sub = idx & 3;
            uint32_t so = (uint32_t)(row * RSTRIDE + sub * 16);
            CPA16(st + so,         Ah + (size_t)(m0 + row) * CC + k0 + sub * 8);
            CPA16(st + ABT + so,   Al + (size_t)(m0 + row) * CC + k0 + sub * 8);
            CPA16(st + 2*ABT + so, Bh + (size_t)(n0 + row) * CC + k0 + sub * 8);
            CPA16(st + 3*ABT + so, Bl + (size_t)(n0 + row) * CC + k0 + sub * 8);
        }
    };

    load_chunk(0, 0);
    asm volatile("cp.async.commit_group;" ::: "memory");
    load_chunk(1, 1);
    asm volatile("cp.async.commit_group;" ::: "memory");

    int g = lane >> 3, r = lane & 7;
    const int NCH = CC / 32;
    for (int c = 0; c < NCH; c++) {
        int s = c % 3;
        asm volatile("cp.async.wait_group 1;" ::: "memory");
        __syncthreads();
        uint32_t stg = sb + s * TSTG;
        #pragma unroll
        for (int ks = 0; ks < 2; ks++) {
            uint32_t ah[4][4], al[4][4];
            #pragma unroll
            for (int mt = 0; mt < 4; mt++) {
                uint32_t arow = (uint32_t)(wm * 64 + mt * 16 + r + (g & 1) * 8);
                uint32_t acol = (uint32_t)((2 * ks + (g >> 1)) * 16);
                ldsm4(ah[mt], stg + arow * RSTRIDE + acol);
                ldsm4(al[mt], stg + ABT + arow * RSTRIDE + acol);
            }
            #pragma unroll
            for (int np = 0; np < 2; np++) {
                uint32_t brow = (uint32_t)(wn * 32 + np * 16 + (g >> 1) * 8 + r);
                uint32_t bcol = (uint32_t)((2 * ks + (g & 1)) * 16);
                uint32_t bh[4], bl[4];
                ldsm4(bh, stg + 2*ABT + brow * RSTRIDE + bcol);
                ldsm4(bl, stg + 3*ABT + brow * RSTRIDE + bcol);
                #pragma unroll
                for (int mt = 0; mt < 4; mt++) {
                    mma16816(acc[mt][2 * np],     ah[mt], &bh[0]);
                    mma16816(acc[mt][2 * np + 1], ah[mt], &bh[2]);
                    mma16816(acc[mt][2 * np],     ah[mt], &bl[0]);
                    mma16816(acc[mt][2 * np + 1], ah[mt], &bl[2]);
                    mma16816(acc[mt][2 * np],     al[mt], &bh[0]);
                    mma16816(acc[mt][2 * np + 1], al[mt], &bh[2]);
                }
            }
        }
        if (c + 2 < NCH) load_chunk(c + 2, (c + 2) % 3);
        asm volatile("cp.async.commit_group;" ::: "memory");
    }

    int lrow = lane >> 2, lcol = (lane & 3) * 2;
    float* ab = g_att + (size_t)b * LL * LL;
    #pragma unroll
    for (int mt = 0; mt < 4; mt++)
        #pragma unroll
        for (int nt = 0; nt < 4; nt++)
            #pragma unroll
            for (int e = 0; e < 4; e++) {
                int i = m0 + wm * 64 + mt * 16 + lrow + (e >> 1) * 8;
                int j = n0 + wn * 32 + nt * 8 + lcol + (e & 1);
                if (i < LL && j < LL) ab[(size_t)i * LL + j] = acc[mt][nt][e];
            }
}

__global__ void softmax_kernel() {
    int row = blockIdx.x * blockDim.y + threadIdx.y;
    if (row >= NBL) return;
    int b = row / LL, i = row - b * LL;
    float* e = g_att + (size_t)row * LL;
    int lane = threadIdx.x;
    float mx = -1e30f;
    for (int j = lane; j < LL; j += 32) mx = fmaxf(mx, e[j]);
    #pragma unroll
    for (int o = 16; o; o >>= 1) mx = fmaxf(mx, __shfl_xor_sync(0xffffffffu, mx, o));
    float s = 0.f;
    for (int j = lane; j < LL; j += 32) { float v = __expf(e[j] - mx); e[j] = v; s += v; }
    #pragma unroll
    for (int o = 16; o; o >>= 1) s += __shfl_xor_sync(0xffffffffu, s, o);
    float inv = 1.f / s;
    __nv_bfloat16* ah = g_atth + ((size_t)b * LPAD + i) * JPAD;
    __nv_bfloat16* al = g_attl + ((size_t)b * LPAD + i) * JPAD;
    for (int j = lane; j < JPAD; j += 32) {
        float v = (j < LL) ? e[j] * inv : 0.f;
        bf16split(v, &ah[j], &al[j]);
    }
}

__global__ void vconv() {
    int idx = blockIdx.x * blockDim.x + threadIdx.x;
    if (idx >= BB * CC * JPAD) return;
    int j = idx % JPAD;
    int bc = idx / JPAD;
    int c = bc % CC, b = bc / CC;
    float v = 0.f;
    if (j < LL)
        v = g_v[((size_t)b * CC + c) * LL + j] * g_coeff[2 * CC + c] + g_off[2 * CC + c];
    bf16split(v, &g_vh[idx], &g_vl[idx]);
}

__global__ void __launch_bounds__(256)
out_mma(const float* __restrict__ x, const float* __restrict__ gamma) {
    extern __shared__ char smem[];
    uint32_t sb = s2u(smem);
    int tid = threadIdx.x, wid = tid >> 5, lane = tid & 31;
    int m0 = blockIdx.x * 128, n0 = blockIdx.y * 128, b = blockIdx.z;
    int wm = wid & 1, wn = wid >> 1;
    const __nv_bfloat16* Ah = g_vh + (size_t)b * CC * JPAD;
    const __nv_bfloat16* Al = g_vl + (size_t)b * CC * JPAD;
    const __nv_bfloat16* Bh = g_atth + (size_t)b * LPAD * JPAD;
    const __nv_bfloat16* Bl = g_attl + (size_t)b * LPAD * JPAD;

    float acc[4][4][4];
    #pragma unroll
    for (int mt = 0; mt < 4; mt++)
        #pragma unroll
        for (int nt = 0; nt < 4; nt++)
            #pragma unroll
            for (int e = 0; e < 4; e++) acc[mt][nt][e] = 0.f;

    auto load_chunk = [&](int c, int s) {
        int k0 = c * 32;
        uint32_t st = sb + s * TSTG;
        #pragma unroll
        for (int i = 0; i < 2; i++) {
            int idx = tid + 256 * i;
            int row = idx >> 2, sub = idx & 3;
            uint32_t so = (uint32_t)(row * RSTRIDE + sub * 16);
            CPA16(st + so,         Ah + (size_t)(m0 + row) * JPAD + k0 + sub * 8);
            CPA16(st + ABT + so,   Al + (size_t)(m0 + row) * JPAD + k0 + sub * 8);
            CPA16(st + 2*ABT + so, Bh + (size_t)(n0 + row) * JPAD + k0 + sub * 8);
            CPA16(st + 3*ABT + so, Bl + (size_t)(n0 + row) * JPAD + k0 + sub * 8);
        }
    };

    load_chunk(0, 0);
    asm volatile("cp.async.commit_group;" ::: "memory");
    load_chunk(1, 1);
    asm volatile("cp.async.commit_group;" ::: "memory");

    int g = lane >> 3, r = lane & 7;
    const int NCH = JPAD / 32;
    for (int c = 0; c < NCH; c++) {
        int s = c % 3;
        asm volatile("cp.async.wait_group 1;" ::: "memory");
        __syncthreads();
        uint32_t stg = sb + s * TSTG;
        #pragma unroll
        for (int ks = 0; ks < 2; ks++) {
            uint32_t ah[4][4], al[4][4];
            #pragma unroll
            for (int mt = 0; mt < 4; mt++) {
                uint32_t arow = (uint32_t)(wm * 64 + mt * 16 + r + (g & 1) * 8);
                uint32_t acol = (uint32_t)((2 * ks + (g >> 1)) * 16);
                ldsm4(ah[mt], stg + arow * RSTRIDE + acol);
                ldsm4(al[mt], stg + ABT + arow * RSTRIDE + acol);
            }
            #pragma unroll
            for (int np = 0; np < 2; np++) {
                uint32_t brow = (uint32_t)(wn * 32 + np * 16 + (g >> 1) * 8 + r);
                uint32_t bcol = (uint32_t)((2 * ks + (g & 1)) * 16);
                uint32_t bh[4], bl[4];
                ldsm4(bh, stg + 2*ABT + brow * RSTRIDE + bcol);
                ldsm4(bl, stg + 3*ABT + brow * RSTRIDE + bcol);
                #pragma unroll
                for (int mt = 0; mt < 4; mt++) {
                    mma16816(acc[mt][2 * np],     ah[mt], &bh[0]);
                    mma16816(acc[mt][2 * np + 1], ah[mt], &bh[2]);
                    mma16816(acc[mt][2 * np],     ah[mt], &bl[0]);
                    mma16816(acc[mt][2 * np + 1], ah[mt], &bl[2]);
                    mma16816(acc[mt][2 * np],     al[mt], &bh[0]);
                    mma16816(acc[mt][2 * np + 1], al[mt], &bh[2]);
                }
            }
        }
        if (c + 2 < NCH) load_chunk(c + 2, (c + 2) % 3);
        asm volatile("cp.async.commit_group;" ::: "memory");
    }

    float g0 = gamma[0];
    int lrow = lane >> 2, lcol = (lane & 3) * 2;
    #pragma unroll
    for (int mt = 0; mt < 4; mt++)
        #pragma unroll
        for (int nt = 0; nt < 4; nt++)
            #pragma unroll
            for (int e = 0; e < 4; e++) {
                int cch = m0 + wm * 64 + mt * 16 + lrow + (e >> 1) * 8;
                int i = n0 + wn * 32 + nt * 8 + lcol + (e & 1);
                if (i < LL) {
                    size_t o = ((size_t)b * CC + cch) * LL + i;
                    g_y[o] = g0 * x[o] + acc[mt][nt][e];
                }
            }
}

__global__ void final_norm(float* __restrict__ out) {
    int idx = blockIdx.x * blockDim.x + threadIdx.x;
    if (idx >= BB * CC * LL) return;
    int c = (idx / LL) % CC;
    out[idx] = g_y[idx] * g_coeff[3 * CC + c] + g_off[3 * CC + c];
}

extern "C" void kernel_launch(void* const* d_in, const int* in_sizes, int n_in,
                              void* d_out, int out_size) {
    const float* x      = (const float*)d_in[0];
    const float* Wq     = (const float*)d_in[1];
    const float* Wk     = (const float*)d_in[2];
    const float* Wv     = (const float*)d_in[3];
    const float* bnq_s  = (const float*)d_in[4];
    const float* bnq_b  = (const float*)d_in[5];
    const float* bnk_s  = (const float*)d_in[6];
    const float* bnk_b  = (const float*)d_in[7];
    const float* bnv_s  = (const float*)d_in[8];
    const float* bnv_b  = (const float*)d_in[9];
    const float* gamma  = (const float*)d_in[10];
    const float* freqs  = (const float*)d_in[11];
    const float* norm_s = (const float*)d_in[12];
    const float* norm_b = (const float*)d_in[13];
    float* out = (float*)d_out;

    cudaFuncSetAttribute(conv_mma, cudaFuncAttributeMaxDynamicSharedMemorySize, SMEMSZ);
    cudaFuncSetAttribute(energy_mma, cudaFuncAttributeMaxDynamicSharedMemorySize, TSMEM);
    cudaFuncSetAttribute(out_mma, cudaFuncAttributeMaxDynamicSharedMemorySize, TSMEM);

    build_zT<<<(ZT_MAIN + ZT_PADS + 255) / 256, 256>>>(x);
    build_W_all<<<(MDIM * KDIM + 255) / 256, 256>>>(Wq, Wk, Wv);
    build_bias<<<MDIM, 96>>>(Wq, Wk, Wv);
    conv_mma<<<dim3(MDIM / 128, NP / NT), 512, SMEMSZ>>>();
    bn_stats3<<<dim3(CC, 3), 256>>>(bnq_s, bnq_b, bnk_s, bnk_b, bnv_s, bnv_b);
    rope_kernel<<<dim3(7, 12, BB), 256>>>(freqs);
    vconv<<<(BB * CC * JPAD + 255) / 256, 256>>>();
    energy_mma<<<dim3(2, 2, BB), 256, TSMEM>>>();
    softmax_kernel<<<dim3((NBL + 3) / 4), dim3(32, 4)>>>();
    out_mma<<<dim3(CC / 128, 2, BB), 256, TSMEM>>>(x, gamma);
    bn_stats<<<CC, 256>>>(3, norm_s, norm_b);
    final_norm<<<(BB * CC * LL + 255) / 256, 256>>>(out);
}

// round 15
// speedup vs baseline: 1.0253x; 1.0253x over previous
#include <cuda_runtime.h>
#include <cuda_bf16.h>
#include <math.h>
#include <stdint.h>

#define BB 64
#define CC 768
#define LL 197
#define NBL (BB*LL)
#define EPSV 1e-5f
#define MDIM 2304
#define KDIM 6912
#define KCH  2304
#define NROW 200
#define NP   (BB*NROW)
#define NZROWS (NP+4)
#define NCHUNK 216
#define RSTRIDE 80
#define A_BYTES (128*RSTRIDE)
#define B_BYTES (256*RSTRIDE)
#define STG_BYTES (2*A_BYTES + 2*B_BYTES)
#define SMEMSZ (3*STG_BYTES)
#define LPAD 256
#define JPAD 224
#define ABT (128*RSTRIDE)
#define TSTG (4*128*RSTRIDE)
#define TSMEM (3*TSTG)

__device__ __nv_bfloat16 g_zhi[(size_t)NZROWS * KCH];
__device__ __nv_bfloat16 g_zlo[(size_t)NZROWS * KCH];
__device__ __nv_bfloat16 g_whi[(size_t)MDIM * KDIM];
__device__ __nv_bfloat16 g_wlo[(size_t)MDIM * KDIM];
__device__ float g_bias[3][MDIM];
__device__ float g_q[(size_t)BB * CC * LL];
__device__ float g_k[(size_t)BB * CC * LL];
__device__ float g_v[(size_t)BB * CC * LL];
__device__ __nv_bfloat16 g_Qh[(size_t)BB * LPAD * CC];
__device__ __nv_bfloat16 g_Ql[(size_t)BB * LPAD * CC];
__device__ __nv_bfloat16 g_Kh[(size_t)BB * LPAD * CC];
__device__ __nv_bfloat16 g_Kl[(size_t)BB * LPAD * CC];
__device__ float g_att[(size_t)BB * LL * LL];
__device__ __nv_bfloat16 g_atth[(size_t)BB * LPAD * JPAD];
__device__ __nv_bfloat16 g_attl[(size_t)BB * LPAD * JPAD];
__device__ __nv_bfloat16 g_vh[(size_t)BB * CC * JPAD];
__device__ __nv_bfloat16 g_vl[(size_t)BB * CC * JPAD];
__device__ float g_y[(size_t)BB * CC * LL];
__device__ float g_coeff[4 * CC];
__device__ float g_off[4 * CC];

__device__ __forceinline__ uint32_t s2u(const void* p) {
    uint32_t a;
    asm("{ .reg .u64 t; cvta.to.shared.u64 t, %1; cvt.u32.u64 %0, t; }" : "=r"(a) : "l"(p));
    return a;
}
#define CPA16(dst, src) \
    asm volatile("cp.async.cg.shared.global [%0], [%1], 16;" :: "r"(dst), "l"(src) : "memory")
__device__ __forceinline__ void ldsm4(uint32_t* r, uint32_t addr) {
    asm volatile("ldmatrix.sync.aligned.m8n8.x4.shared.b16 {%0,%1,%2,%3}, [%4];"
                 : "=r"(r[0]), "=r"(r[1]), "=r"(r[2]), "=r"(r[3]) : "r"(addr));
}
__device__ __forceinline__ void mma16816(float* c, const uint32_t* a, const uint32_t* b) {
    asm volatile(
        "mma.sync.aligned.m16n8k16.row.col.f32.bf16.bf16.f32 "
        "{%0,%1,%2,%3}, {%4,%5,%6,%7}, {%8,%9}, {%0,%1,%2,%3};"
        : "+f"(c[0]), "+f"(c[1]), "+f"(c[2]), "+f"(c[3])
        : "r"(a[0]), "r"(a[1]), "r"(a[2]), "r"(a[3]), "r"(b[0]), "r"(b[1]));
}
__device__ __forceinline__ void bf16split(float v, __nv_bfloat16* hi, __nv_bfloat16* lo) {
    __nv_bfloat16 h = __float2bfloat16(v);
    *hi = h;
    *lo = __float2bfloat16(v - __bfloat162float(h));
}

// ---- build_zT with pad-zeroing merged ----
#define ZT_MAIN (BB*CC*LL)
#define ZT_PADS (196*KCH)
__global__ void build_zT(const float* __restrict__ x) {
    int idx = blockIdx.x * blockDim.x + threadIdx.x;
    if (idx < ZT_MAIN) {
        int l = idx % LL;
        int bc = idx / LL;
        int c = bc % CC, b = bc / CC;
        float t = tanhf(x[idx]);
        float T[3];
        T[0] = t; T[1] = 2.f * t * t - 1.f; T[2] = 2.f * t * T[1] - t;
        size_t base = ((size_t)(b * NROW + l + 1)) * KCH + c * 3;
        #pragma unroll
        for (int d = 0; d < 3; d++)
            bf16split(T[d], &g_zhi[base + d], &g_zlo[base + d]);
    } else if (idx < ZT_MAIN + ZT_PADS) {
        int p = idx - ZT_MAIN;
        int rid = p / KCH, c = p - rid * KCH;
        int row;
        if (rid < 192) {
            int b = rid / 3, s = rid % 3;
            row = b * NROW + (s == 0 ? 0 : (s == 1 ? 198 : 199));
        } else row = NP + (rid - 192);
        size_t o = (size_t)row * KCH + c;
        g_zhi[o] = __float2bfloat16(0.f);
        g_zlo[o] = __float2bfloat16(0.f);
    }
}

__global__ void build_W_all(const float* __restrict__ Wq, const float* __restrict__ Wk,
                            const float* __restrict__ Wv) {
    int idx = blockIdx.x * blockDim.x + threadIdx.x;
    if (idx >= MDIM * KDIM) return;
    int k = idx % KDIM;
    int gm = idx / KDIM;
    int which = gm / CC, co = gm - which * CC;
    const float* W = (which == 0) ? Wq : (which == 1) ? Wk : Wv;
    int tap = k / KCH, rem = k - tap * KCH;
    int ci = rem / 3, d = rem - ci * 3 + 1;
    float v = W[(size_t)co * (3072 * 3) + (size_t)(ci * 4 + d) * 3 + tap];
    size_t o = (size_t)gm * KDIM + k;
    bf16split(v, &g_whi[o], &g_wlo[o]);
}

__global__ void build_bias(const float* __restrict__ Wq, const float* __restrict__ Wk,
                           const float* __restrict__ Wv) {
    int gm = blockIdx.x;
    int which = gm / CC, co = gm - which * CC;
    const float* W = (which == 0) ? Wq : (which == 1) ? Wk : Wv;
    int tap = threadIdx.x >> 5, lane = threadIdx.x & 31;
    float s = 0.f;
    for (int ci = lane; ci < CC; ci += 32)
        s += W[(size_t)co * (3072 * 3) + (size_t)(ci * 4) * 3 + tap];
    #pragma unroll
    for (int o = 16; o; o >>= 1) s += __shfl_xor_sync(0xffffffffu, s, o);
    if (lane == 0) g_bias[tap][gm] = s;
}

// bf16x3 conv-GEMM, 512 threads, 128x256 tile, 3-stage, loads AFTER compute (R13)
__global__ void __launch_bounds__(512, 1)
conv_mma() {
    extern __shared__ char smem[];
    uint32_t sb = s2u(smem);
    int tid = threadIdx.x, wid = tid >> 5, lane = tid & 31;
    int m0 = blockIdx.x * 128, n0 = blockIdx.y * 256;
    int which = m0 / CC, co0 = m0 - which * CC;
    int wm = wid & 1;
    int wn = wid >> 1;

    float acc[4][4][4];
    #pragma unroll
    for (int mt = 0; mt < 4; mt++)
        #pragma unroll
        for (int nt = 0; nt < 4; nt++)
            #pragma unroll
            for (int e = 0; e < 4; e++) acc[mt][nt][e] = 0.f;

    auto load_chunk = [&](int c, int s) {
        int tap = c / 72;
        int koff = (c - tap * 72) * 32;
        uint32_t st = sb + s * STG_BYTES;
        size_t kb = (size_t)tap * KCH + koff;
        #pragma unroll
        for (int i = 0; i < 2; i++) {
            int idx = tid + 512 * i;
            int row = idx >> 3, sub = idx & 7;
            int arr = sub >> 2, j = sub & 3;
            const __nv_bfloat16* src =
                (arr ? g_wlo : g_whi) + (size_t)(m0 + row) * KDIM + kb + j * 8;
            CPA16(st + arr * A_BYTES + row * RSTRIDE + j * 16, src);
        }
        #pragma unroll
        for (int i = 0; i < 4; i++) {
            int idx = tid + 512 * i;
            int row = idx >> 3, sub = idx & 7;
            int arr = sub >> 2, j = sub & 3;
            const __nv_bfloat16* src =
                (arr ? g_zlo : g_zhi) + (size_t)(n0 + row + tap) * KCH + koff + j * 8;
            CPA16(st + 2 * A_BYTES + arr * B_BYTES + row * RSTRIDE + j * 16, src);
        }
    };

    load_chunk(0, 0);
    asm volatile("cp.async.commit_group;" ::: "memory");
    load_chunk(1, 1);
    asm volatile("cp.async.commit_group;" ::: "memory");

    int g = lane >> 3, r = lane & 7;

    for (int c = 0; c < NCHUNK; c++) {
        int s = c % 3;
        asm volatile("cp.async.wait_group 1;" ::: "memory");
        __syncthreads();
        uint32_t stg = sb + s * STG_BYTES;
        #pragma unroll
        for (int ks = 0; ks < 2; ks++) {
            uint32_t ah[4][4], al[4][4];
            #pragma unroll
            for (int mt = 0; mt < 4; mt++) {
                uint32_t arow = (uint32_t)(wm * 64 + mt * 16 + r + (g & 1) * 8);
                uint32_t acol = (uint32_t)((2 * ks + (g >> 1)) * 16);
                ldsm4(ah[mt], stg + arow * RSTRIDE + acol);
                ldsm4(al[mt], stg + A_BYTES + arow * RSTRIDE + acol);
            }
            #pragma unroll
            for (int np = 0; np < 2; np++) {
                uint32_t brow = (uint32_t)(wn * 32 + np * 16 + (g >> 1) * 8 + r);
                uint32_t bcol = (uint32_t)((2 * ks + (g & 1)) * 16);
                uint32_t bh[4], bl[4];
                ldsm4(bh, stg + 2 * A_BYTES + brow * RSTRIDE + bcol);
                ldsm4(bl, stg + 2 * A_BYTES + B_BYTES + brow * RSTRIDE + bcol);
                #pragma unroll
                for (int mt = 0; mt < 4; mt++) {
                    mma16816(acc[mt][2 * np],     ah[mt], &bh[0]);
                    mma16816(acc[mt][2 * np + 1], ah[mt], &bh[2]);
                    mma16816(acc[mt][2 * np],     ah[mt], &bl[0]);
                    mma16816(acc[mt][2 * np + 1], ah[mt], &bl[2]);
                    mma16816(acc[mt][2 * np],     al[mt], &bh[0]);
                    mma16816(acc[mt][2 * np + 1], al[mt], &bh[2]);
                }
            }
        }
        if (c + 2 < NCHUNK) load_chunk(c + 2, (c + 2) % 3);
        asm volatile("cp.async.commit_group;" ::: "memory");
    }

    float* outp = (which == 0) ? g_q : (which == 1) ? g_k : g_v;
    int lrow = lane >> 2, lcol = (lane & 3) * 2;
    #pragma unroll
    for (int mt = 0; mt < 4; mt++) {
        int m_lo = wm * 64 + mt * 16 + lrow;
        float b0[2], b1[2], b2[2];
        #pragma unroll
        for (int h = 0; h < 2; h++) {
            int gm = m0 + m_lo + h * 8;
            b0[h] = g_bias[0][gm]; b1[h] = g_bias[1][gm]; b2[h] = g_bias[2][gm];
        }
        #pragma unroll
        for (int nt = 0; nt < 4; nt++) {
            int ncol = n0 + wn * 32 + nt * 8 + lcol;
            #pragma unroll
            for (int e = 0; e < 4; e++) {
                int h = e >> 1;
                int m = m_lo + h * 8;
                int n = ncol + (e & 1);
                int b = n / NROW;
                int l = n - b * NROW;
                if (l < LL) {
                    float bias = b0[h] + b1[h] + b2[h];
                    if (l == 0)   bias -= b0[h];
                    if (l == 196) bias -= b2[h];
                    outp[((size_t)b * CC + (co0 + m)) * LL + l] = acc[mt][nt][e] + bias;
                }
            }
        }
    }
}

// ---- BN stats, 512 threads ----
__global__ void bn_stats3(const float* __restrict__ sq, const float* __restrict__ bq,
                          const float* __restrict__ sk, const float* __restrict__ bk,
                          const float* __restrict__ sv, const float* __restrict__ bv) {
    int sel = blockIdx.y;
    const float* in = (sel == 0) ? g_q : (sel == 1) ? g_k : g_v;
    const float* scale = (sel == 0) ? sq : (sel == 1) ? sk : sv;
    const float* bias  = (sel == 0) ? bq : (sel == 1) ? bk : bv;
    int c = blockIdx.x;
    float s = 0.f, s2 = 0.f;
    for (int i = threadIdx.x; i < NBL; i += 512) {
        int b = i / LL, l = i - b * LL;
        float v = in[((size_t)b * CC + c) * LL + l];
        s += v; s2 += v * v;
    }
    __shared__ float sh[512], sh2[512];
    sh[threadIdx.x] = s; sh2[threadIdx.x] = s2;
    __syncthreads();
    for (int st = 256; st > 0; st >>= 1) {
        if (threadIdx.x < st) { sh[threadIdx.x] += sh[threadIdx.x + st]; sh2[threadIdx.x] += sh2[threadIdx.x + st]; }
        __syncthreads();
    }
    if (threadIdx.x == 0) {
        float m = sh[0] / (float)NBL;
        float var = sh2[0] / (float)NBL - m * m;
        float cf = scale[c] * rsqrtf(var + EPSV);
        g_coeff[sel * CC + c] = cf;
        g_off[sel * CC + c]   = bias[c] - m * cf;
    }
}

__global__ void bn_stats(int sel, const float* __restrict__ scale, const float* __restrict__ bias) {
    int c = blockIdx.x;
    float s = 0.f, s2 = 0.f;
    for (int i = threadIdx.x; i < NBL; i += 512) {
        int b = i / LL, l = i - b * LL;
        float v = g_y[((size_t)b * CC + c) * LL + l];
        s += v; s2 += v * v;
    }
    __shared__ float sh[512], sh2[512];
    sh[threadIdx.x] = s; sh2[threadIdx.x] = s2;
    __syncthreads();
    for (int st = 256; st > 0; st >>= 1) {
        if (threadIdx.x < st) { sh[threadIdx.x] += sh[threadIdx.x + st]; sh2[threadIdx.x] += sh2[threadIdx.x + st]; }
        __syncthreads();
    }
    if (threadIdx.x == 0) {
        float m = sh[0] / (float)NBL;
        float var = sh2[0] / (float)NBL - m * m;
        float cf = scale[c] * rsqrtf(var + EPSV);
        g_coeff[sel * CC + c] = cf;
        g_off[sel * CC + c]   = bias[c] - m * cf;
    }
}

__global__ void rope_kernel(const float* __restrict__ freqs) {
    int b  = blockIdx.z;
    int c0 = blockIdx.y * 64;
    int l0 = blockIdx.x * 32;
    __shared__ float s[64][33];
    for (int which = 0; which < 2; which++) {
        const float* src = which ? g_k : g_q;
        const float* cf  = g_coeff + which * CC;
        const float* of  = g_off   + which * CC;
        __nv_bfloat16* dh = which ? g_Kh : g_Qh;
        __nv_bfloat16* dl = which ? g_Kl : g_Ql;
        for (int t = threadIdx.x; t < 64 * 32; t += 256) {
            int cl = t / 32, ll = t - cl * 32;
            int c = c0 + cl, l = l0 + ll;
            float v = 0.f;
            if (l < LL) v = src[((size_t)b * CC + c) * LL + l] * cf[c] + of[c];
            s[cl][ll] = v;
        }
        __syncthreads();
        for (int t = threadIdx.x; t < 32 * 32; t += 256) {
            int ll = t / 32, dl2 = t - ll * 32;
            int l = l0 + ll;
            if (l < LL) {
                int d = c0 / 2 + dl2;
                float a  = s[2 * dl2][ll];
                float bb = s[2 * dl2 + 1][ll];
                float ra, rb;
                if (l == 0) { ra = a; rb = bb; }
                else {
                    float nf = (float)(l - 1);
                    float tx = fmodf(nf, 14.0f);
                    float ty = floorf(nf / 14.0f);
                    float ang = tx * freqs[d] + ty * freqs[384 + d];
                    float sn, cs;
                    sincosf(ang, &sn, &cs);
                    ra = a * cs - bb * sn;
                    rb = a * sn + bb * cs;
                }
                size_t o = ((size_t)b * LPAD + l) * CC + c0 + 2 * dl2;
                bf16split(ra, &dh[o], &dl[o]);
                bf16split(rb, &dh[o + 1], &dl[o + 1]);
            }
        }
        __syncthreads();
    }
}

__global__ void __launch_bounds__(256)
energy_mma() {
    extern __shared__ char smem[];
    uint32_t sb = s2u(smem);
    int tid = threadIdx.x, wid = tid >> 5, lane = tid & 31;
    int m0 = blockIdx.x * 128, n0 = blockIdx.y * 128, b = blockIdx.z;
    int wm = wid & 1, wn = wid >> 1;
    const __nv_bfloat16* Ah = g_Qh + (size_t)b * LPAD * CC;
    const __nv_bfloat16* Al = g_Ql + (size_t)b * LPAD * CC;
    const __nv_bfloat16* Bh = g_Kh + (size_t)b * LPAD * CC;
    const __nv_bfloat16* Bl = g_Kl + (size_t)b * LPAD * CC;

    float acc[4][4][4];
    #pragma unroll
    for (int mt = 0; mt < 4; mt++)
        #pragma unroll
        for (int nt = 0; nt < 4; nt++)
            #pragma unroll
            for (int e = 0; e < 4; e++) acc[mt][nt][e] = 0.f;

    auto load_chunk = [&](int c, int s) {
        int k0 = c * 32;
        uint32_t st = sb + s * TSTG;
        #pragma unroll
        for (int i = 0; i < 2; i++) {
            int idx = tid + 256 * i;
            int row = idx >> 2, sub = idx & 3;
            uint32_t so = (uint32_t)(row * RSTRIDE + sub * 16);
            CPA16(st + so,         Ah + (size_t)(m0 + row) * CC + k0 + sub * 8);
            CPA16(st + ABT + so,   Al + (size_t)(m0 + row) * CC + k0 + sub * 8);
            CPA16(st + 2*ABT + so, Bh + (size_t)(n0 + row) * CC + k0 + sub * 8);
            CPA16(st + 3*ABT + so, Bl + (size_t)(n0 + row) * CC + k0 + sub * 8);
        }
    };

    load_chunk(0, 0);
    asm volatile("cp.async.commit_group;" ::: "memory");
    load_chunk(1, 1);
    asm volatile("cp.async.commit_group;" ::: "memory");

    int g = lane >> 3, r = lane & 7;
    const int NCH = CC / 32;
    for (int c = 0; c < NCH; c++) {
        int s = c % 3;
        asm volatile("cp.async.wait_group 1;" ::: "memory");
        __syncthreads();
        uint32_t stg = sb + s * TSTG;
        #pragma unroll
        for (int ks = 0; ks < 2; ks++) {
            uint32_t ah[4][4], al[4][4];
            #pragma unroll
            for (int mt = 0; mt < 4; mt++) {
                uint32_t arow = (uint32_t)(wm * 64 + mt * 16 + r + (g & 1) * 8);
                uint32_t acol = (uint32_t)((2 * ks + (g >> 1)) * 16);
                ldsm4(ah[mt], stg + arow * RSTRIDE + acol);
                ldsm4(al[mt], stg + ABT + arow * RSTRIDE + acol);
            }
            #pragma unroll
            for (int np = 0; np < 2; np++) {
                uint32_t brow = (uint32_t)(wn * 32 + np * 16 + (g >> 1) * 8 + r);
                uint32_t bcol = (uint32_t)((2 * ks + (g & 1)) * 16);
                uint32_t bh[4], bl[4];
                ldsm4(bh, stg + 2*ABT + brow * RSTRIDE + bcol);
                ldsm4(bl, stg + 3*ABT + brow * RSTRIDE + bcol);
                #pragma unroll
                for (int mt = 0; mt < 4; mt++) {
                    mma16816(acc[mt][2 * np],     ah[mt], &bh[0]);
                    mma16816(acc[mt][2 * np + 1], ah[mt], &bh[2]);
                    mma16816(acc[mt][2 * np],     ah[mt], &bl[0]);
                    mma16816(acc[mt][2 * np + 1], ah[mt], &bl[2]);
                    mma16816(acc[mt][2 * np],     al[mt], &bh[0]);
                    mma16816(acc[mt][2 * np + 1], al[mt], &bh[2]);
                }
            }
        }
        if (c + 2 < NCH) load_chunk(c + 2, (c + 2) % 3);
        asm volatile("cp.async.commit_group;" ::: "memory");
    }

    int lrow = lane >> 2, lcol = (lane & 3) * 2;
    float* ab = g_att + (size_t)b * LL * LL;
    #pragma unroll
    for (int mt = 0; mt < 4; mt++)
        #pragma unroll
        for (int nt = 0; nt < 4; nt++)
            #pragma unroll
            for (int e = 0; e < 4; e++) {
                int i = m0 + wm * 64 + mt * 16 + lrow + (e >> 1) * 8;
                int j = n0 + wn * 32 + nt * 8 + lcol + (e & 1);
                if (i < LL && j < LL) ab[(size_t)i * LL + j] = acc[mt][nt][e];
            }
}

__global__ void softmax_kernel() {
    int row = blockIdx.x * blockDim.y + threadIdx.y;
    if (row >= NBL) return;
    int b = row / LL, i = row - b * LL;
    float* e = g_att + (size_t)row * LL;
    int lane = threadIdx.x;
    float mx = -1e30f;
    for (int j = lane; j < LL; j += 32) mx = fmaxf(mx, e[j]);
    #pragma unroll
    for (int o = 16; o; o >>= 1) mx = fmaxf(mx, __shfl_xor_sync(0xffffffffu, mx, o));
    float s = 0.f;
    for (int j = lane; j < LL; j += 32) { float v = __expf(e[j] - mx); e[j] = v; s += v; }
    #pragma unroll
    for (int o = 16; o; o >>= 1) s += __shfl_xor_sync(0xffffffffu, s, o);
    float inv = 1.f / s;
    __nv_bfloat16* ah = g_atth + ((size_t)b * LPAD + i) * JPAD;
    __nv_bfloat16* al = g_attl + ((size_t)b * LPAD + i) * JPAD;
    for (int j = lane; j < JPAD; j += 32) {
        float v = (j < LL) ? e[j] * inv : 0.f;
        bf16split(v, &ah[j], &al[j]);
    }
}

__global__ void vconv() {
    for (int idx = blockIdx.x * blockDim.x + threadIdx.x;
         idx < BB * CC * JPAD; idx += gridDim.x * blockDim.x) {
        int j = idx % JPAD;
        int bc = idx / JPAD;
        int c = bc % CC, b = bc / CC;
        float v = 0.f;
        if (j < LL)
            v = g_v[((size_t)b * CC + c) * LL + j] * g_coeff[2 * CC + c] + g_off[2 * CC + c];
        bf16split(v, &g_vh[idx], &g_vl[idx]);
    }
}

__global__ void __launch_bounds__(256)
out_mma(const float* __restrict__ x, const float* __restrict__ gamma) {
    extern __shared__ char smem[];
    uint32_t sb = s2u(smem);
    int tid = threadIdx.x, wid = tid >> 5, lane = tid & 31;
    int m0 = blockIdx.x * 128, n0 = blockIdx.y * 128, b = blockIdx.z;
    int wm = wid & 1, wn = wid >> 1;
    const __nv_bfloat16* Ah = g_vh + (size_t)b * CC * JPAD;
    const __nv_bfloat16* Al = g_vl + (size_t)b * CC * JPAD;
    const __nv_bfloat16* Bh = g_atth + (size_t)b * LPAD * JPAD;
    const __nv_bfloat16* Bl = g_attl + (size_t)b * LPAD * JPAD;

    float acc[4][4][4];
    #pragma unroll
    for (int mt = 0; mt < 4; mt++)
        #pragma unroll
        for (int nt = 0; nt < 4; nt++)
            #pragma unroll
            for (int e = 0; e < 4; e++) acc[mt][nt][e] = 0.f;

    auto load_chunk = [&](int c, int s) {
        int k0 = c * 32;
        uint32_t st = sb + s * TSTG;
        #pragma unroll
        for (int i = 0; i < 2; i++) {
            int idx = tid + 256 * i;
            int row = idx >> 2, sub = idx & 3;
            uint32_t so = (uint32_t)(row * RSTRIDE + sub * 16);
            CPA16(st + so,         Ah + (size_t)(m0 + row) * JPAD + k0 + sub * 8);
            CPA16(st + ABT + so,   Al + (size_t)(m0 + row) * JPAD + k0 + sub * 8);
            CPA16(st + 2*ABT + so, Bh + (size_t)(n0 + row) * JPAD + k0 + sub * 8);
            CPA16(st + 3*ABT + so, Bl + (size_t)(n0 + row) * JPAD + k0 + sub * 8);
        }
    };

    load_chunk(0, 0);
    asm volatile("cp.async.commit_group;" ::: "memory");
    load_chunk(1, 1);
    asm volatile("cp.async.commit_group;" ::: "memory");

    int g = lane >> 3, r = lane & 7;
    const int NCH = JPAD / 32;
    for (int c = 0; c < NCH; c++) {
        int s = c % 3;
        asm volatile("cp.async.wait_group 1;" ::: "memory");
        __syncthreads();
        uint32_t stg = sb + s * TSTG;
        #pragma unroll
        for (int ks = 0; ks < 2; ks++) {
            uint32_t ah[4][4], al[4][4];
            #pragma unroll
            for (int mt = 0; mt < 4; mt++) {
                uint32_t arow = (uint32_t)(wm * 64 + mt * 16 + r + (g & 1) * 8);
                uint32_t acol = (uint32_t)((2 * ks + (g >> 1)) * 16);
                ldsm4(ah[mt], stg + arow * RSTRIDE + acol);
                ldsm4(al[mt], stg + ABT + arow * RSTRIDE + acol);
            }
            #pragma unroll
            for (int np = 0; np < 2; np++) {
                uint32_t brow = (uint32_t)(wn * 32 + np * 16 + (g >> 1) * 8 + r);
                uint32_t bcol = (uint32_t)((2 * ks + (g & 1)) * 16);
                uint32_t bh[4], bl[4];
                ldsm4(bh, stg + 2*ABT + brow * RSTRIDE + bcol);
                ldsm4(bl, stg + 3*ABT + brow * RSTRIDE + bcol);
                #pragma unroll
                for (int mt = 0; mt < 4; mt++) {
                    mma16816(acc[mt][2 * np],     ah[mt], &bh[0]);
                    mma16816(acc[mt][2 * np + 1], ah[mt], &bh[2]);
                    mma16816(acc[mt][2 * np],     ah[mt], &bl[0]);
                    mma16816(acc[mt][2 * np + 1], ah[mt], &bl[2]);
                    mma16816(acc[mt][2 * np],     al[mt], &bh[0]);
                    mma16816(acc[mt][2 * np + 1], al[mt], &bh[2]);
                }
            }
        }
        if (c + 2 < NCH) load_chunk(c + 2, (c + 2) % 3);
        asm volatile("cp.async.commit_group;" ::: "memory");
    }

    float g0 = gamma[0];
    int lrow = lane >> 2, lcol = (lane & 3) * 2;
    #pragma unroll
    for (int mt = 0; mt < 4; mt++)
        #pragma unroll
        for (int nt = 0; nt < 4; nt++)
            #pragma unroll
            for (int e = 0; e < 4; e++) {
                int cch = m0 + wm * 64 + mt * 16 + lrow + (e >> 1) * 8;
                int i = n0 + wn * 32 + nt * 8 + lcol + (e & 1);
                if (i < LL) {
                    size_t o = ((size_t)b * CC + cch) * LL + i;
                    g_y[o] = g0 * x[o] + acc[mt][nt][e];
                }
            }
}

__global__ void final_norm(float* __restrict__ out) {
    int idx = blockIdx.x * blockDim.x + threadIdx.x;
    if (idx >= BB * CC * LL) return;
    int c = (idx / LL) % CC;
    out[idx] = g_y[idx] * g_coeff[3 * CC + c] + g_off[3 * CC + c];
}

extern "C" void kernel_launch(void* const* d_in, const int* in_sizes, int n_in,
                              void* d_out, int out_size) {
    const float* x      = (const float*)d_in[0];
    const float* Wq     = (const float*)d_in[1];
    const float* Wk     = (const float*)d_in[2];
    const float* Wv     = (const float*)d_in[3];
    const float* bnq_s  = (const float*)d_in[4];
    const float* bnq_b  = (const float*)d_in[5];
    const float* bnk_s  = (const float*)d_in[6];
    const float* bnk_b  = (const float*)d_in[7];
    const float* bnv_s  = (const float*)d_in[8];
    const float* bnv_b  = (const float*)d_in[9];
    const float* gamma  = (const float*)d_in[10];
    const float* freqs  = (const float*)d_in[11];
    const float* norm_s = (const float*)d_in[12];
    const float* norm_b = (const float*)d_in[13];
    float* out = (float*)d_out;

    cudaFuncSetAttribute(conv_mma, cudaFuncAttributeMaxDynamicSharedMemorySize, SMEMSZ);
    cudaFuncSetAttribute(energy_mma, cudaFuncAttributeMaxDynamicSharedMemorySize, TSMEM);
    cudaFuncSetAttribute(out_mma, cudaFuncAttributeMaxDynamicSharedMemorySize, TSMEM);

    build_zT<<<(ZT_MAIN + ZT_PADS + 255) / 256, 256>>>(x);
    build_W_all<<<(MDIM * KDIM + 255) / 256, 256>>>(Wq, Wk, Wv);
    build_bias<<<MDIM, 96>>>(Wq, Wk, Wv);
    conv_mma<<<dim3(MDIM / 128, NP / 256), 512, SMEMSZ>>>();
    bn_stats3<<<dim3(CC, 3), 512>>>(bnq_s, bnq_b, bnk_s, bnk_b, bnv_s, bnv_b);
    rope_kernel<<<dim3(7, 12, BB), 256>>>(freqs);
    vconv<<<1184, 256>>>();
    energy_mma<<<dim3(2, 2, BB), 256, TSMEM>>>();
    softmax_kernel<<<dim3((NBL + 3) / 4), dim3(32, 4)>>>();
    out_mma<<<dim3(CC / 128, 2, BB), 256, TSMEM>>>(x, gamma);
    bn_stats<<<CC, 512>>>(3, norm_s, norm_b);
    final_norm<<<(BB * CC * LL + 255) / 256, 256>>>(out);
}

// round 16
// speedup vs baseline: 1.0270x; 1.0017x over previous
#include <cuda_runtime.h>
#include <cuda_bf16.h>
#include <math.h>
#include <stdint.h>

#define BB 64
#define CC 768
#define LL 197
#define NBL (BB*LL)
#define EPSV 1e-5f
#define MDIM 2304
#define KDIM 6912
#define KCH  2304
#define NROW 200
#define NP   (BB*NROW)
#define NZROWS (NP+4)
#define NCHUNK 216
#define RSTRIDE 80
#define A_BYTES (128*RSTRIDE)
#define B_BYTES (256*RSTRIDE)
#define STG_BYTES (2*A_BYTES + 2*B_BYTES)
#define SMEMSZ (3*STG_BYTES)
#define LPAD 256
#define JPAD 224
#define ABT (128*RSTRIDE)
#define TSTG (4*128*RSTRIDE)
#define TSMEM (3*TSTG)

__device__ __nv_bfloat16 g_zhi[(size_t)NZROWS * KCH];
__device__ __nv_bfloat16 g_zlo[(size_t)NZROWS * KCH];
__device__ __nv_bfloat16 g_whi[(size_t)MDIM * KDIM];
__device__ __nv_bfloat16 g_wlo[(size_t)MDIM * KDIM];
__device__ float g_bias[3][MDIM];
__device__ float g_q[(size_t)BB * CC * LL];
__device__ float g_k[(size_t)BB * CC * LL];
__device__ float g_v[(size_t)BB * CC * LL];
__device__ __nv_bfloat16 g_Qh[(size_t)BB * LPAD * CC];
__device__ __nv_bfloat16 g_Ql[(size_t)BB * LPAD * CC];
__device__ __nv_bfloat16 g_Kh[(size_t)BB * LPAD * CC];
__device__ __nv_bfloat16 g_Kl[(size_t)BB * LPAD * CC];
__device__ float g_att[(size_t)BB * LL * LL];
__device__ __nv_bfloat16 g_atth[(size_t)BB * LPAD * JPAD];
__device__ __nv_bfloat16 g_attl[(size_t)BB * LPAD * JPAD];
__device__ __nv_bfloat16 g_vh[(size_t)BB * CC * JPAD];
__device__ __nv_bfloat16 g_vl[(size_t)BB * CC * JPAD];
__device__ float g_y[(size_t)BB * CC * LL];
__device__ float g_coeff[4 * CC];
__device__ float g_off[4 * CC];

__device__ __forceinline__ uint32_t s2u(const void* p) {
    uint32_t a;
    asm("{ .reg .u64 t; cvta.to.shared.u64 t, %1; cvt.u32.u64 %0, t; }" : "=r"(a) : "l"(p));
    return a;
}
#define CPA16(dst, src) \
    asm volatile("cp.async.cg.shared.global [%0], [%1], 16;" :: "r"(dst), "l"(src) : "memory")
__device__ __forceinline__ void ldsm4(uint32_t* r, uint32_t addr) {
    asm volatile("ldmatrix.sync.aligned.m8n8.x4.shared.b16 {%0,%1,%2,%3}, [%4];"
                 : "=r"(r[0]), "=r"(r[1]), "=r"(r[2]), "=r"(r[3]) : "r"(addr));
}
__device__ __forceinline__ void mma16816(float* c, const uint32_t* a, const uint32_t* b) {
    asm volatile(
        "mma.sync.aligned.m16n8k16.row.col.f32.bf16.bf16.f32 "
        "{%0,%1,%2,%3}, {%4,%5,%6,%7}, {%8,%9}, {%0,%1,%2,%3};"
        : "+f"(c[0]), "+f"(c[1]), "+f"(c[2]), "+f"(c[3])
        : "r"(a[0]), "r"(a[1]), "r"(a[2]), "r"(a[3]), "r"(b[0]), "r"(b[1]));
}
__device__ __forceinline__ void bf16split(float v, __nv_bfloat16* hi, __nv_bfloat16* lo) {
    __nv_bfloat16 h = __float2bfloat16(v);
    *hi = h;
    *lo = __float2bfloat16(v - __bfloat162float(h));
}

// ---- build_zT with pad-zeroing merged ----
#define ZT_MAIN (BB*CC*LL)
#define ZT_PADS (196*KCH)
__global__ void build_zT(const float* __restrict__ x) {
    int idx = blockIdx.x * blockDim.x + threadIdx.x;
    if (idx < ZT_MAIN) {
        int l = idx % LL;
        int bc = idx / LL;
        int c = bc % CC, b = bc / CC;
        float t = tanhf(x[idx]);
        float T[3];
        T[0] = t; T[1] = 2.f * t * t - 1.f; T[2] = 2.f * t * T[1] - t;
        size_t base = ((size_t)(b * NROW + l + 1)) * KCH + c * 3;
        #pragma unroll
        for (int d = 0; d < 3; d++)
            bf16split(T[d], &g_zhi[base + d], &g_zlo[base + d]);
    } else if (idx < ZT_MAIN + ZT_PADS) {
        int p = idx - ZT_MAIN;
        int rid = p / KCH, c = p - rid * KCH;
        int row;
        if (rid < 192) {
            int b = rid / 3, s = rid % 3;
            row = b * NROW + (s == 0 ? 0 : (s == 1 ? 198 : 199));
        } else row = NP + (rid - 192);
        size_t o = (size_t)row * KCH + c;
        g_zhi[o] = __float2bfloat16(0.f);
        g_zlo[o] = __float2bfloat16(0.f);
    }
}

__global__ void build_W_all(const float* __restrict__ Wq, const float* __restrict__ Wk,
                            const float* __restrict__ Wv) {
    int idx = blockIdx.x * blockDim.x + threadIdx.x;
    if (idx >= MDIM * KDIM) return;
    int k = idx % KDIM;
    int gm = idx / KDIM;
    int which = gm / CC, co = gm - which * CC;
    const float* W = (which == 0) ? Wq : (which == 1) ? Wk : Wv;
    int tap = k / KCH, rem = k - tap * KCH;
    int ci = rem / 3, d = rem - ci * 3 + 1;
    float v = W[(size_t)co * (3072 * 3) + (size_t)(ci * 4 + d) * 3 + tap];
    size_t o = (size_t)gm * KDIM + k;
    bf16split(v, &g_whi[o], &g_wlo[o]);
}

__global__ void build_bias(const float* __restrict__ Wq, const float* __restrict__ Wk,
                           const float* __restrict__ Wv) {
    int gm = blockIdx.x;
    int which = gm / CC, co = gm - which * CC;
    const float* W = (which == 0) ? Wq : (which == 1) ? Wk : Wv;
    int tap = threadIdx.x >> 5, lane = threadIdx.x & 31;
    float s = 0.f;
    for (int ci = lane; ci < CC; ci += 32)
        s += W[(size_t)co * (3072 * 3) + (size_t)(ci * 4) * 3 + tap];
    #pragma unroll
    for (int o = 16; o; o >>= 1) s += __shfl_xor_sync(0xffffffffu, s, o);
    if (lane == 0) g_bias[tap][gm] = s;
}

// bf16x3 conv-GEMM, 512 threads, 128x256 tile, 3-stage, loads AFTER compute
__global__ void __launch_bounds__(512, 1)
conv_mma() {
    extern __shared__ char smem[];
    uint32_t sb = s2u(smem);
    int tid = threadIdx.x, wid = tid >> 5, lane = tid & 31;
    int m0 = blockIdx.x * 128, n0 = blockIdx.y * 256;
    int which = m0 / CC, co0 = m0 - which * CC;
    int wm = wid & 1;
    int wn = wid >> 1;

    float acc[4][4][4];
    #pragma unroll
    for (int mt = 0; mt < 4; mt++)
        #pragma unroll
        for (int nt = 0; nt < 4; nt++)
            #pragma unroll
            for (int e = 0; e < 4; e++) acc[mt][nt][e] = 0.f;

    auto load_chunk = [&](int c, int s) {
        int tap = c / 72;
        int koff = (c - tap * 72) * 32;
        uint32_t st = sb + s * STG_BYTES;
        size_t kb = (size_t)tap * KCH + koff;
        #pragma unroll
        for (int i = 0; i < 2; i++) {
            int idx = tid + 512 * i;
            int row = idx >> 3, sub = idx & 7;
            int arr = sub >> 2, j = sub & 3;
            const __nv_bfloat16* src =
                (arr ? g_wlo : g_whi) + (size_t)(m0 + row) * KDIM + kb + j * 8;
            CPA16(st + arr * A_BYTES + row * RSTRIDE + j * 16, src);
        }
        #pragma unroll
        for (int i = 0; i < 4; i++) {
            int idx = tid + 512 * i;
            int row = idx >> 3, sub = idx & 7;
            int arr = sub >> 2, j = sub & 3;
            const __nv_bfloat16* src =
                (arr ? g_zlo : g_zhi) + (size_t)(n0 + row + tap) * KCH + koff + j * 8;
            CPA16(st + 2 * A_BYTES + arr * B_BYTES + row * RSTRIDE + j * 16, src);
        }
    };

    load_chunk(0, 0);
    asm volatile("cp.async.commit_group;" ::: "memory");
    load_chunk(1, 1);
    asm volatile("cp.async.commit_group;" ::: "memory");

    int g = lane >> 3, r = lane & 7;

    for (int c = 0; c < NCHUNK; c++) {
        int s = c % 3;
        asm volatile("cp.async.wait_group 1;" ::: "memory");
        __syncthreads();
        uint32_t stg = sb + s * STG_BYTES;
        #pragma unroll
        for (int ks = 0; ks < 2; ks++) {
            uint32_t ah[4][4], al[4][4];
            #pragma unroll
            for (int mt = 0; mt < 4; mt++) {
                uint32_t arow = (uint32_t)(wm * 64 + mt * 16 + r + (g & 1) * 8);
                uint32_t acol = (uint32_t)((2 * ks + (g >> 1)) * 16);
                ldsm4(ah[mt], stg + arow * RSTRIDE + acol);
                ldsm4(al[mt], stg + A_BYTES + arow * RSTRIDE + acol);
            }
            #pragma unroll
            for (int np = 0; np < 2; np++) {
                uint32_t brow = (uint32_t)(wn * 32 + np * 16 + (g >> 1) * 8 + r);
                uint32_t bcol = (uint32_t)((2 * ks + (g & 1)) * 16);
                uint32_t bh[4], bl[4];
                ldsm4(bh, stg + 2 * A_BYTES + brow * RSTRIDE + bcol);
                ldsm4(bl, stg + 2 * A_BYTES + B_BYTES + brow * RSTRIDE + bcol);
                #pragma unroll
                for (int mt = 0; mt < 4; mt++) {
                    mma16816(acc[mt][2 * np],     ah[mt], &bh[0]);
                    mma16816(acc[mt][2 * np + 1], ah[mt], &bh[2]);
                    mma16816(acc[mt][2 * np],     ah[mt], &bl[0]);
                    mma16816(acc[mt][2 * np + 1], ah[mt], &bl[2]);
                    mma16816(acc[mt][2 * np],     al[mt], &bh[0]);
                    mma16816(acc[mt][2 * np + 1], al[mt], &bh[2]);
                }
            }
        }
        if (c + 2 < NCHUNK) load_chunk(c + 2, (c + 2) % 3);
        asm volatile("cp.async.commit_group;" ::: "memory");
    }

    float* outp = (which == 0) ? g_q : (which == 1) ? g_k : g_v;
    int lrow = lane >> 2, lcol = (lane & 3) * 2;
    #pragma unroll
    for (int mt = 0; mt < 4; mt++) {
        int m_lo = wm * 64 + mt * 16 + lrow;
        float b0[2], b1[2], b2[2];
        #pragma unroll
        for (int h = 0; h < 2; h++) {
            int gm = m0 + m_lo + h * 8;
            b0[h] = g_bias[0][gm]; b1[h] = g_bias[1][gm]; b2[h] = g_bias[2][gm];
        }
        #pragma unroll
        for (int nt = 0; nt < 4; nt++) {
            int ncol = n0 + wn * 32 + nt * 8 + lcol;
            #pragma unroll
            for (int e = 0; e < 4; e++) {
                int h = e >> 1;
                int m = m_lo + h * 8;
                int n = ncol + (e & 1);
                int b = n / NROW;
                int l = n - b * NROW;
                if (l < LL) {
                    float bias = b0[h] + b1[h] + b2[h];
                    if (l == 0)   bias -= b0[h];
                    if (l == 196) bias -= b2[h];
                    outp[((size_t)b * CC + (co0 + m)) * LL + l] = acc[mt][nt][e] + bias;
                }
            }
        }
    }
}

// ---- BN stats, 512 threads ----
__global__ void bn_stats3(const float* __restrict__ sq, const float* __restrict__ bq,
                          const float* __restrict__ sk, const float* __restrict__ bk,
                          const float* __restrict__ sv, const float* __restrict__ bv) {
    int sel = blockIdx.y;
    const float* in = (sel == 0) ? g_q : (sel == 1) ? g_k : g_v;
    const float* scale = (sel == 0) ? sq : (sel == 1) ? sk : sv;
    const float* bias  = (sel == 0) ? bq : (sel == 1) ? bk : bv;
    int c = blockIdx.x;
    float s = 0.f, s2 = 0.f;
    for (int i = threadIdx.x; i < NBL; i += 512) {
        int b = i / LL, l = i - b * LL;
        float v = in[((size_t)b * CC + c) * LL + l];
        s += v; s2 += v * v;
    }
    __shared__ float sh[512], sh2[512];
    sh[threadIdx.x] = s; sh2[threadIdx.x] = s2;
    __syncthreads();
    for (int st = 256; st > 0; st >>= 1) {
        if (threadIdx.x < st) { sh[threadIdx.x] += sh[threadIdx.x + st]; sh2[threadIdx.x] += sh2[threadIdx.x + st]; }
        __syncthreads();
    }
    if (threadIdx.x == 0) {
        float m = sh[0] / (float)NBL;
        float var = sh2[0] / (float)NBL - m * m;
        float cf = scale[c] * rsqrtf(var + EPSV);
        g_coeff[sel * CC + c] = cf;
        g_off[sel * CC + c]   = bias[c] - m * cf;
    }
}

__global__ void bn_stats(int sel, const float* __restrict__ scale, const float* __restrict__ bias) {
    int c = blockIdx.x;
    float s = 0.f, s2 = 0.f;
    for (int i = threadIdx.x; i < NBL; i += 512) {
        int b = i / LL, l = i - b * LL;
        float v = g_y[((size_t)b * CC + c) * LL + l];
        s += v; s2 += v * v;
    }
    __shared__ float sh[512], sh2[512];
    sh[threadIdx.x] = s; sh2[threadIdx.x] = s2;
    __syncthreads();
    for (int st = 256; st > 0; st >>= 1) {
        if (threadIdx.x < st) { sh[threadIdx.x] += sh[threadIdx.x + st]; sh2[threadIdx.x] += sh2[threadIdx.x + st]; }
        __syncthreads();
    }
    if (threadIdx.x == 0) {
        float m = sh[0] / (float)NBL;
        float var = sh2[0] / (float)NBL - m * m;
        float cf = scale[c] * rsqrtf(var + EPSV);
        g_coeff[sel * CC + c] = cf;
        g_off[sel * CC + c]   = bias[c] - m * cf;
    }
}

__global__ void rope_kernel(const float* __restrict__ freqs) {
    int b  = blockIdx.z;
    int c0 = blockIdx.y * 64;
    int l0 = blockIdx.x * 32;
    __shared__ float s[64][33];
    for (int which = 0; which < 2; which++) {
        const float* src = which ? g_k : g_q;
        const float* cf  = g_coeff + which * CC;
        const float* of  = g_off   + which * CC;
        __nv_bfloat16* dh = which ? g_Kh : g_Qh;
        __nv_bfloat16* dl = which ? g_Kl : g_Ql;
        for (int t = threadIdx.x; t < 64 * 32; t += 256) {
            int cl = t / 32, ll = t - cl * 32;
            int c = c0 + cl, l = l0 + ll;
            float v = 0.f;
            if (l < LL) v = src[((size_t)b * CC + c) * LL + l] * cf[c] + of[c];
            s[cl][ll] = v;
        }
        __syncthreads();
        for (int t = threadIdx.x; t < 32 * 32; t += 256) {
            int ll = t / 32, dl2 = t - ll * 32;
            int l = l0 + ll;
            if (l < LL) {
                int d = c0 / 2 + dl2;
                float a  = s[2 * dl2][ll];
                float bb = s[2 * dl2 + 1][ll];
                float ra, rb;
                if (l == 0) { ra = a; rb = bb; }
                else {
                    float nf = (float)(l - 1);
                    float tx = fmodf(nf, 14.0f);
                    float ty = floorf(nf / 14.0f);
                    float ang = tx * freqs[d] + ty * freqs[384 + d];
                    float sn, cs;
                    sincosf(ang, &sn, &cs);
                    ra = a * cs - bb * sn;
                    rb = a * sn + bb * cs;
                }
                size_t o = ((size_t)b * LPAD + l) * CC + c0 + 2 * dl2;
                bf16split(ra, &dh[o], &dl[o]);
                bf16split(rb, &dh[o + 1], &dl[o + 1]);
            }
        }
        __syncthreads();
    }
}

__global__ void __launch_bounds__(256)
energy_mma() {
    extern __shared__ char smem[];
    uint32_t sb = s2u(smem);
    int tid = threadIdx.x, wid = tid >> 5, lane = tid & 31;
    int m0 = blockIdx.x * 128, n0 = blockIdx.y * 128, b = blockIdx.z;
    int wm = wid & 1, wn = wid >> 1;
    const __nv_bfloat16* Ah = g_Qh + (size_t)b * LPAD * CC;
    const __nv_bfloat16* Al = g_Ql + (size_t)b * LPAD * CC;
    const __nv_bfloat16* Bh = g_Kh + (size_t)b * LPAD * CC;
    const __nv_bfloat16* Bl = g_Kl + (size_t)b * LPAD * CC;

    float acc[4][4][4];
    #pragma unroll
    for (int mt = 0; mt < 4; mt++)
        #pragma unroll
        for (int nt = 0; nt < 4; nt++)
            #pragma unroll
            for (int e = 0; e < 4; e++) acc[mt][nt][e] = 0.f;

    auto load_chunk = [&](int c, int s) {
        int k0 = c * 32;
        uint32_t st = sb + s * TSTG;
        #pragma unroll
        for (int i = 0; i < 2; i++) {
            int idx = tid + 256 * i;
            int row = idx >> 2, sub = idx & 3;
            uint32_t so = (uint32_t)(row * RSTRIDE + sub * 16);
            CPA16(st + so,         Ah + (size_t)(m0 + row) * CC + k0 + sub * 8);
            CPA16(st + ABT + so,   Al + (size_t)(m0 + row) * CC + k0 + sub * 8);
            CPA16(st + 2*ABT + so, Bh + (size_t)(n0 + row) * CC + k0 + sub * 8);
            CPA16(st + 3*ABT + so, Bl + (size_t)(n0 + row) * CC + k0 + sub * 8);
        }
    };

    load_chunk(0, 0);
    asm volatile("cp.async.commit_group;" ::: "memory");
    load_chunk(1, 1);
    asm volatile("cp.async.commit_group;" ::: "memory");

    int g = lane >> 3, r = lane & 7;
    const int NCH = CC / 32;
    for (int c = 0; c < NCH; c++) {
        int s = c % 3;
        asm volatile("cp.async.wait_group 1;" ::: "memory");
        __syncthreads();
        uint32_t stg = sb + s * TSTG;
        #pragma unroll
        for (int ks = 0; ks < 2; ks++) {
            uint32_t ah[4][4], al[4][4];
            #pragma unroll
            for (int mt = 0; mt < 4; mt++) {
                uint32_t arow = (uint32_t)(wm * 64 + mt * 16 + r + (g & 1) * 8);
                uint32_t acol = (uint32_t)((2 * ks + (g >> 1)) * 16);
                ldsm4(ah[mt], stg + arow * RSTRIDE + acol);
                ldsm4(al[mt], stg + ABT + arow * RSTRIDE + acol);
            }
            #pragma unroll
            for (int np = 0; np < 2; np++) {
                uint32_t brow = (uint32_t)(wn * 32 + np * 16 + (g >> 1) * 8 + r);
                uint32_t bcol = (uint32_t)((2 * ks + (g & 1)) * 16);
                uint32_t bh[4], bl[4];
                ldsm4(bh, stg + 2*ABT + brow * RSTRIDE + bcol);
                ldsm4(bl, stg + 3*ABT + brow * RSTRIDE + bcol);
                #pragma unroll
                for (int mt = 0; mt < 4; mt++) {
                    mma16816(acc[mt][2 * np],     ah[mt], &bh[0]);
                    mma16816(acc[mt][2 * np + 1], ah[mt], &bh[2]);
                    mma16816(acc[mt][2 * np],     ah[mt], &bl[0]);
                    mma16816(acc[mt][2 * np + 1], ah[mt], &bl[2]);
                    mma16816(acc[mt][2 * np],     al[mt], &bh[0]);
                    mma16816(acc[mt][2 * np + 1], al[mt], &bh[2]);
                }
            }
        }
        if (c + 2 < NCH) load_chunk(c + 2, (c + 2) % 3);
        asm volatile("cp.async.commit_group;" ::: "memory");
    }

    int lrow = lane >> 2, lcol = (lane & 3) * 2;
    float* ab = g_att + (size_t)b * LL * LL;
    #pragma unroll
    for (int mt = 0; mt < 4; mt++)
        #pragma unroll
        for (int nt = 0; nt < 4; nt++)
            #pragma unroll
            for (int e = 0; e < 4; e++) {
                int i = m0 + wm * 64 + mt * 16 + lrow + (e >> 1) * 8;
                int j = n0 + wn * 32 + nt * 8 + lcol + (e & 1);
                if (i < LL && j < LL) ab[(size_t)i * LL + j] = acc[mt][nt][e];
            }
}

__global__ void softmax_kernel() {
    int row = blockIdx.x * blockDim.y + threadIdx.y;
    if (row >= NBL) return;
    int b = row / LL, i = row - b * LL;
    float* e = g_att + (size_t)row * LL;
    int lane = threadIdx.x;
    float mx = -1e30f;
    for (int j = lane; j < LL; j += 32) mx = fmaxf(mx, e[j]);
    #pragma unroll
    for (int o = 16; o; o >>= 1) mx = fmaxf(mx, __shfl_xor_sync(0xffffffffu, mx, o));
    float s = 0.f;
    for (int j = lane; j < LL; j += 32) { float v = __expf(e[j] - mx); e[j] = v; s += v; }
    #pragma unroll
    for (int o = 16; o; o >>= 1) s += __shfl_xor_sync(0xffffffffu, s, o);
    float inv = 1.f / s;
    __nv_bfloat16* ah = g_atth + ((size_t)b * LPAD + i) * JPAD;
    __nv_bfloat16* al = g_attl + ((size_t)b * LPAD + i) * JPAD;
    for (int j = lane; j < JPAD; j += 32) {
        float v = (j < LL) ? e[j] * inv : 0.f;
        bf16split(v, &ah[j], &al[j]);
    }
}

__global__ void vconv() {
    for (int idx = blockIdx.x * blockDim.x + threadIdx.x;
         idx < BB * CC * JPAD; idx += gridDim.x * blockDim.x) {
        int j = idx % JPAD;
        int bc = idx / JPAD;
        int c = bc % CC, b = bc / CC;
        float v = 0.f;
        if (j < LL)
            v = g_v[((size_t)b * CC + c) * LL + j] * g_coeff[2 * CC + c] + g_off[2 * CC + c];
        bf16split(v, &g_vh[idx], &g_vl[idx]);
    }
}

__global__ void __launch_bounds__(256)
out_mma(const float* __restrict__ x, const float* __restrict__ gamma) {
    extern __shared__ char smem[];
    uint32_t sb = s2u(smem);
    int tid = threadIdx.x, wid = tid >> 5, lane = tid & 31;
    int m0 = blockIdx.x * 128, n0 = blockIdx.y * 128, b = blockIdx.z;
    int wm = wid & 1, wn = wid >> 1;
    const __nv_bfloat16* Ah = g_vh + (size_t)b * CC * JPAD;
    const __nv_bfloat16* Al = g_vl + (size_t)b * CC * JPAD;
    const __nv_bfloat16* Bh = g_atth + (size_t)b * LPAD * JPAD;
    const __nv_bfloat16* Bl = g_attl + (size_t)b * LPAD * JPAD;

    float acc[4][4][4];
    #pragma unroll
    for (int mt = 0; mt < 4; mt++)
        #pragma unroll
        for (int nt = 0; nt < 4; nt++)
            #pragma unroll
            for (int e = 0; e < 4; e++) acc[mt][nt][e] = 0.f;

    auto load_chunk = [&](int c, int s) {
        int k0 = c * 32;
        uint32_t st = sb + s * TSTG;
        #pragma unroll
        for (int i = 0; i < 2; i++) {
            int idx = tid + 256 * i;
            int row = idx >> 2, sub = idx & 3;
            uint32_t so = (uint32_t)(row * RSTRIDE + sub * 16);
            CPA16(st + so,         Ah + (size_t)(m0 + row) * JPAD + k0 + sub * 8);
            CPA16(st + ABT + so,   Al + (size_t)(m0 + row) * JPAD + k0 + sub * 8);
            CPA16(st + 2*ABT + so, Bh + (size_t)(n0 + row) * JPAD + k0 + sub * 8);
            CPA16(st + 3*ABT + so, Bl + (size_t)(n0 + row) * JPAD + k0 + sub * 8);
        }
    };

    load_chunk(0, 0);
    asm volatile("cp.async.commit_group;" ::: "memory");
    load_chunk(1, 1);
    asm volatile("cp.async.commit_group;" ::: "memory");

    int g = lane >> 3, r = lane & 7;
    const int NCH = JPAD / 32;
    for (int c = 0; c < NCH; c++) {
        int s = c % 3;
        asm volatile("cp.async.wait_group 1;" ::: "memory");
        __syncthreads();
        uint32_t stg = sb + s * TSTG;
        #pragma unroll
        for (int ks = 0; ks < 2; ks++) {
            uint32_t ah[4][4], al[4][4];
            #pragma unroll
            for (int mt = 0; mt < 4; mt++) {
                uint32_t arow = (uint32_t)(wm * 64 + mt * 16 + r + (g & 1) * 8);
                uint32_t acol = (uint32_t)((2 * ks + (g >> 1)) * 16);
                ldsm4(ah[mt], stg + arow * RSTRIDE + acol);
                ldsm4(al[mt], stg + ABT + arow * RSTRIDE + acol);
            }
            #pragma unroll
            for (int np = 0; np < 2; np++) {
                uint32_t brow = (uint32_t)(wn * 32 + np * 16 + (g >> 1) * 8 + r);
                uint32_t bcol = (uint32_t)((2 * ks + (g & 1)) * 16);
                uint32_t bh[4], bl[4];
                ldsm4(bh, stg + 2*ABT + brow * RSTRIDE + bcol);
                ldsm4(bl, stg + 3*ABT + brow * RSTRIDE + bcol);
                #pragma unroll
                for (int mt = 0; mt < 4; mt++) {
                    mma16816(acc[mt][2 * np],     ah[mt], &bh[0]);
                    mma16816(acc[mt][2 * np + 1], ah[mt], &bh[2]);
                    mma16816(acc[mt][2 * np],     ah[mt], &bl[0]);
                    mma16816(acc[mt][2 * np + 1], ah[mt], &bl[2]);
                    mma16816(acc[mt][2 * np],     al[mt], &bh[0]);
                    mma16816(acc[mt][2 * np + 1], al[mt], &bh[2]);
                }
            }
        }
        if (c + 2 < NCH) load_chunk(c + 2, (c + 2) % 3);
        asm volatile("cp.async.commit_group;" ::: "memory");
    }

    float g0 = gamma[0];
    int lrow = lane >> 2, lcol = (lane & 3) * 2;
    #pragma unroll
    for (int mt = 0; mt < 4; mt++)
        #pragma unroll
        for (int nt = 0; nt < 4; nt++)
            #pragma unroll
            for (int e = 0; e < 4; e++) {
                int cch = m0 + wm * 64 + mt * 16 + lrow + (e >> 1) * 8;
                int i = n0 + wn * 32 + nt * 8 + lcol + (e & 1);
                if (i < LL) {
                    size_t o = ((size_t)b * CC + cch) * LL + i;
                    g_y[o] = g0 * x[o] + acc[mt][nt][e];
                }
            }
}

__global__ void final_norm(float* __restrict__ out) {
    int base = (blockIdx.x * blockDim.x + threadIdx.x) * 2;
    #pragma unroll
    for (int u = 0; u < 2; u++) {
        int idx = base + u;
        if (idx < BB * CC * LL) {
            int c = (idx / LL) % CC;
            out[idx] = g_y[idx] * g_coeff[3 * CC + c] + g_off[3 * CC + c];
        }
    }
}

extern "C" void kernel_launch(void* const* d_in, const int* in_sizes, int n_in,
                              void* d_out, int out_size) {
    const float* x      = (const float*)d_in[0];
    const float* Wq     = (const float*)d_in[1];
    const float* Wk     = (const float*)d_in[2];
    const float* Wv     = (const float*)d_in[3];
    const float* bnq_s  = (const float*)d_in[4];
    const float* bnq_b  = (const float*)d_in[5];
    const float* bnk_s  = (const float*)d_in[6];
    const float* bnk_b  = (const float*)d_in[7];
    const float* bnv_s  = (const float*)d_in[8];
    const float* bnv_b  = (const float*)d_in[9];
    const float* gamma  = (const float*)d_in[10];
    const float* freqs  = (const float*)d_in[11];
    const float* norm_s = (const float*)d_in[12];
    const float* norm_b = (const float*)d_in[13];
    float* out = (float*)d_out;

    cudaFuncSetAttribute(conv_mma, cudaFuncAttributeMaxDynamicSharedMemorySize, SMEMSZ);
    cudaFuncSetAttribute(energy_mma, cudaFuncAttributeMaxDynamicSharedMemorySize, TSMEM);
    cudaFuncSetAttribute(out_mma, cudaFuncAttributeMaxDynamicSharedMemorySize, TSMEM);

    build_zT<<<(ZT_MAIN + ZT_PADS + 255) / 256, 256>>>(x);
    build_W_all<<<(MDIM * KDIM + 255) / 256, 256>>>(Wq, Wk, Wv);
    build_bias<<<MDIM, 96>>>(Wq, Wk, Wv);
    conv_mma<<<dim3(MDIM / 128, NP / 256), 512, SMEMSZ>>>();
    bn_stats3<<<dim3(CC, 3), 512>>>(bnq_s, bnq_b, bnk_s, bnk_b, bnv_s, bnv_b);
    rope_kernel<<<dim3(7, 12, BB), 256>>>(freqs);
    vconv<<<1184, 256>>>();
    energy_mma<<<dim3(2, 2, BB), 256, TSMEM>>>();
    softmax_kernel<<<dim3((NBL + 7) / 8), dim3(32, 8)>>>();
    out_mma<<<dim3(CC / 128, 2, BB), 256, TSMEM>>>(x, gamma);
    bn_stats<<<CC, 512>>>(3, norm_s, norm_b);
    final_norm<<<(BB * CC * LL / 2 + 255) / 256, 256>>>(out);
}

// round 17
// speedup vs baseline: 1.0284x; 1.0013x over previous
#include <cuda_runtime.h>
#include <cuda_bf16.h>
#include <math.h>
#include <stdint.h>

#define BB 64
#define CC 768
#define LL 197
#define NBL (BB*LL)
#define EPSV 1e-5f
#define MDIM 2304
#define KDIM 6912
#define KCH  2304
#define NROW 200
#define NP   (BB*NROW)
#define NZROWS (NP+4)
#define NCHUNK 216
#define RSTRIDE 80
#define A_BYTES (128*RSTRIDE)
#define B_BYTES (256*RSTRIDE)
#define STG_BYTES (2*A_BYTES + 2*B_BYTES)
#define SMEMSZ (3*STG_BYTES)
#define LPAD 256
#define JPAD 224
#define ABT (128*RSTRIDE)
#define TSTG (4*128*RSTRIDE)
#define TSMEM (3*TSTG)

__device__ __nv_bfloat16 g_zhi[(size_t)NZROWS * KCH];
__device__ __nv_bfloat16 g_zlo[(size_t)NZROWS * KCH];
__device__ __nv_bfloat16 g_whi[(size_t)MDIM * KDIM];
__device__ __nv_bfloat16 g_wlo[(size_t)MDIM * KDIM];
__device__ float g_bias[3][MDIM];
__device__ float g_q[(size_t)BB * CC * LL];
__device__ float g_k[(size_t)BB * CC * LL];
__device__ float g_v[(size_t)BB * CC * LL];
__device__ __nv_bfloat16 g_Qh[(size_t)BB * LPAD * CC];
__device__ __nv_bfloat16 g_Ql[(size_t)BB * LPAD * CC];
__device__ __nv_bfloat16 g_Kh[(size_t)BB * LPAD * CC];
__device__ __nv_bfloat16 g_Kl[(size_t)BB * LPAD * CC];
__device__ float g_att[(size_t)BB * LL * LL];
__device__ __nv_bfloat16 g_atth[(size_t)BB * LPAD * JPAD];
__device__ __nv_bfloat16 g_attl[(size_t)BB * LPAD * JPAD];
__device__ __nv_bfloat16 g_vh[(size_t)BB * CC * JPAD];
__device__ __nv_bfloat16 g_vl[(size_t)BB * CC * JPAD];
__device__ float g_y[(size_t)BB * CC * LL];
__device__ float g_coeff[4 * CC];
__device__ float g_off[4 * CC];

__device__ __forceinline__ uint32_t s2u(const void* p) {
    uint32_t a;
    asm("{ .reg .u64 t; cvta.to.shared.u64 t, %1; cvt.u32.u64 %0, t; }" : "=r"(a) : "l"(p));
    return a;
}
#define CPA16(dst, src) \
    asm volatile("cp.async.cg.shared.global [%0], [%1], 16;" :: "r"(dst), "l"(src) : "memory")
__device__ __forceinline__ void ldsm4(uint32_t* r, uint32_t addr) {
    asm volatile("ldmatrix.sync.aligned.m8n8.x4.shared.b16 {%0,%1,%2,%3}, [%4];"
                 : "=r"(r[0]), "=r"(r[1]), "=r"(r[2]), "=r"(r[3]) : "r"(addr));
}
__device__ __forceinline__ void mma16816(float* c, const uint32_t* a, const uint32_t* b) {
    asm volatile(
        "mma.sync.aligned.m16n8k16.row.col.f32.bf16.bf16.f32 "
        "{%0,%1,%2,%3}, {%4,%5,%6,%7}, {%8,%9}, {%0,%1,%2,%3};"
        : "+f"(c[0]), "+f"(c[1]), "+f"(c[2]), "+f"(c[3])
        : "r"(a[0]), "r"(a[1]), "r"(a[2]), "r"(a[3]), "r"(b[0]), "r"(b[1]));
}
__device__ __forceinline__ void bf16split(float v, __nv_bfloat16* hi, __nv_bfloat16* lo) {
    __nv_bfloat16 h = __float2bfloat16(v);
    *hi = h;
    *lo = __float2bfloat16(v - __bfloat162float(h));
}

// ---- build_zT with pad-zeroing merged ----
#define ZT_MAIN (BB*CC*LL)
#define ZT_PADS (196*KCH)
__global__ void build_zT(const float* __restrict__ x) {
    int idx = blockIdx.x * blockDim.x + threadIdx.x;
    if (idx < ZT_MAIN) {
        int l = idx % LL;
        int bc = idx / LL;
        int c = bc % CC, b = bc / CC;
        float t = tanhf(x[idx]);
        float T[3];
        T[0] = t; T[1] = 2.f * t * t - 1.f; T[2] = 2.f * t * T[1] - t;
        size_t base = ((size_t)(b * NROW + l + 1)) * KCH + c * 3;
        #pragma unroll
        for (int d = 0; d < 3; d++)
            bf16split(T[d], &g_zhi[base + d], &g_zlo[base + d]);
    } else if (idx < ZT_MAIN + ZT_PADS) {
        int p = idx - ZT_MAIN;
        int rid = p / KCH, c = p - rid * KCH;
        int row;
        if (rid < 192) {
            int b = rid / 3, s = rid % 3;
            row = b * NROW + (s == 0 ? 0 : (s == 1 ? 198 : 199));
        } else row = NP + (rid - 192);
        size_t o = (size_t)row * KCH + c;
        g_zhi[o] = __float2bfloat16(0.f);
        g_zlo[o] = __float2bfloat16(0.f);
    }
}

__global__ void build_W_all(const float* __restrict__ Wq, const float* __restrict__ Wk,
                            const float* __restrict__ Wv) {
    int idx = blockIdx.x * blockDim.x + threadIdx.x;
    if (idx >= MDIM * KDIM) return;
    int k = idx % KDIM;
    int gm = idx / KDIM;
    int which = gm / CC, co = gm - which * CC;
    const float* W = (which == 0) ? Wq : (which == 1) ? Wk : Wv;
    int tap = k / KCH, rem = k - tap * KCH;
    int ci = rem / 3, d = rem - ci * 3 + 1;
    float v = W[(size_t)co * (3072 * 3) + (size_t)(ci * 4 + d) * 3 + tap];
    size_t o = (size_t)gm * KDIM + k;
    bf16split(v, &g_whi[o], &g_wlo[o]);
}

__global__ void build_bias(const float* __restrict__ Wq, const float* __restrict__ Wk,
                           const float* __restrict__ Wv) {
    int gm = blockIdx.x;
    int which = gm / CC, co = gm - which * CC;
    const float* W = (which == 0) ? Wq : (which == 1) ? Wk : Wv;
    int tap = threadIdx.x >> 5, lane = threadIdx.x & 31;
    float s = 0.f;
    for (int ci = lane; ci < CC; ci += 32)
        s += W[(size_t)co * (3072 * 3) + (size_t)(ci * 4) * 3 + tap];
    #pragma unroll
    for (int o = 16; o; o >>= 1) s += __shfl_xor_sync(0xffffffffu, s, o);
    if (lane == 0) g_bias[tap][gm] = s;
}

// bf16x3 conv-GEMM, 512 threads, 128x256 tile, 3-stage, loads AFTER compute
__global__ void __launch_bounds__(512, 1)
conv_mma() {
    extern __shared__ char smem[];
    uint32_t sb = s2u(smem);
    int tid = threadIdx.x, wid = tid >> 5, lane = tid & 31;
    int m0 = blockIdx.x * 128, n0 = blockIdx.y * 256;
    int which = m0 / CC, co0 = m0 - which * CC;
    int wm = wid & 1;
    int wn = wid >> 1;

    float acc[4][4][4];
    #pragma unroll
    for (int mt = 0; mt < 4; mt++)
        #pragma unroll
        for (int nt = 0; nt < 4; nt++)
            #pragma unroll
            for (int e = 0; e < 4; e++) acc[mt][nt][e] = 0.f;

    auto load_chunk = [&](int c, int s) {
        int tap = c / 72;
        int koff = (c - tap * 72) * 32;
        uint32_t st = sb + s * STG_BYTES;
        size_t kb = (size_t)tap * KCH + koff;
        #pragma unroll
        for (int i = 0; i < 2; i++) {
            int idx = tid + 512 * i;
            int row = idx >> 3, sub = idx & 7;
            int arr = sub >> 2, j = sub & 3;
            const __nv_bfloat16* src =
                (arr ? g_wlo : g_whi) + (size_t)(m0 + row) * KDIM + kb + j * 8;
            CPA16(st + arr * A_BYTES + row * RSTRIDE + j * 16, src);
        }
        #pragma unroll
        for (int i = 0; i < 4; i++) {
            int idx = tid + 512 * i;
            int row = idx >> 3, sub = idx & 7;
            int arr = sub >> 2, j = sub & 3;
            const __nv_bfloat16* src =
                (arr ? g_zlo : g_zhi) + (size_t)(n0 + row + tap) * KCH + koff + j * 8;
            CPA16(st + 2 * A_BYTES + arr * B_BYTES + row * RSTRIDE + j * 16, src);
        }
    };

    load_chunk(0, 0);
    asm volatile("cp.async.commit_group;" ::: "memory");
    load_chunk(1, 1);
    asm volatile("cp.async.commit_group;" ::: "memory");

    int g = lane >> 3, r = lane & 7;

    for (int c = 0; c < NCHUNK; c++) {
        int s = c % 3;
        asm volatile("cp.async.wait_group 1;" ::: "memory");
        __syncthreads();
        uint32_t stg = sb + s * STG_BYTES;
        #pragma unroll
        for (int ks = 0; ks < 2; ks++) {
            uint32_t ah[4][4], al[4][4];
            #pragma unroll
            for (int mt = 0; mt < 4; mt++) {
                uint32_t arow = (uint32_t)(wm * 64 + mt * 16 + r + (g & 1) * 8);
                uint32_t acol = (uint32_t)((2 * ks + (g >> 1)) * 16);
                ldsm4(ah[mt], stg + arow * RSTRIDE + acol);
                ldsm4(al[mt], stg + A_BYTES + arow * RSTRIDE + acol);
            }
            #pragma unroll
            for (int np = 0; np < 2; np++) {
                uint32_t brow = (uint32_t)(wn * 32 + np * 16 + (g >> 1) * 8 + r);
                uint32_t bcol = (uint32_t)((2 * ks + (g & 1)) * 16);
                uint32_t bh[4], bl[4];
                ldsm4(bh, stg + 2 * A_BYTES + brow * RSTRIDE + bcol);
                ldsm4(bl, stg + 2 * A_BYTES + B_BYTES + brow * RSTRIDE + bcol);
                #pragma unroll
                for (int mt = 0; mt < 4; mt++) {
                    mma16816(acc[mt][2 * np],     ah[mt], &bh[0]);
                    mma16816(acc[mt][2 * np + 1], ah[mt], &bh[2]);
                    mma16816(acc[mt][2 * np],     ah[mt], &bl[0]);
                    mma16816(acc[mt][2 * np + 1], ah[mt], &bl[2]);
                    mma16816(acc[mt][2 * np],     al[mt], &bh[0]);
                    mma16816(acc[mt][2 * np + 1], al[mt], &bh[2]);
                }
            }
        }
        if (c + 2 < NCHUNK) load_chunk(c + 2, (c + 2) % 3);
        asm volatile("cp.async.commit_group;" ::: "memory");
    }

    float* outp = (which == 0) ? g_q : (which == 1) ? g_k : g_v;
    int lrow = lane >> 2, lcol = (lane & 3) * 2;
    #pragma unroll
    for (int mt = 0; mt < 4; mt++) {
        int m_lo = wm * 64 + mt * 16 + lrow;
        float b0[2], b1[2], b2[2];
        #pragma unroll
        for (int h = 0; h < 2; h++) {
            int gm = m0 + m_lo + h * 8;
            b0[h] = g_bias[0][gm]; b1[h] = g_bias[1][gm]; b2[h] = g_bias[2][gm];
        }
        #pragma unroll
        for (int nt = 0; nt < 4; nt++) {
            int ncol = n0 + wn * 32 + nt * 8 + lcol;
            #pragma unroll
            for (int e = 0; e < 4; e++) {
                int h = e >> 1;
                int m = m_lo + h * 8;
                int n = ncol + (e & 1);
                int b = n / NROW;
                int l = n - b * NROW;
                if (l < LL) {
                    float bias = b0[h] + b1[h] + b2[h];
                    if (l == 0)   bias -= b0[h];
                    if (l == 196) bias -= b2[h];
                    outp[((size_t)b * CC + (co0 + m)) * LL + l] = acc[mt][nt][e] + bias;
                }
            }
        }
    }
}

// ---- BN stats, 512 threads ----
__global__ void bn_stats3(const float* __restrict__ sq, const float* __restrict__ bq,
                          const float* __restrict__ sk, const float* __restrict__ bk,
                          const float* __restrict__ sv, const float* __restrict__ bv) {
    int sel = blockIdx.y;
    const float* in = (sel == 0) ? g_q : (sel == 1) ? g_k : g_v;
    const float* scale = (sel == 0) ? sq : (sel == 1) ? sk : sv;
    const float* bias  = (sel == 0) ? bq : (sel == 1) ? bk : bv;
    int c = blockIdx.x;
    float s = 0.f, s2 = 0.f;
    for (int i = threadIdx.x; i < NBL; i += 512) {
        int b = i / LL, l = i - b * LL;
        float v = in[((size_t)b * CC + c) * LL + l];
        s += v; s2 += v * v;
    }
    __shared__ float sh[512], sh2[512];
    sh[threadIdx.x] = s; sh2[threadIdx.x] = s2;
    __syncthreads();
    for (int st = 256; st > 0; st >>= 1) {
        if (threadIdx.x < st) { sh[threadIdx.x] += sh[threadIdx.x + st]; sh2[threadIdx.x] += sh2[threadIdx.x + st]; }
        __syncthreads();
    }
    if (threadIdx.x == 0) {
        float m = sh[0] / (float)NBL;
        float var = sh2[0] / (float)NBL - m * m;
        float cf = scale[c] * rsqrtf(var + EPSV);
        g_coeff[sel * CC + c] = cf;
        g_off[sel * CC + c]   = bias[c] - m * cf;
    }
}

__global__ void bn_stats(int sel, const float* __restrict__ scale, const float* __restrict__ bias) {
    int c = blockIdx.x;
    float s = 0.f, s2 = 0.f;
    for (int i = threadIdx.x; i < NBL; i += 512) {
        int b = i / LL, l = i - b * LL;
        float v = g_y[((size_t)b * CC + c) * LL + l];
        s += v; s2 += v * v;
    }
    __shared__ float sh[512], sh2[512];
    sh[threadIdx.x] = s; sh2[threadIdx.x] = s2;
    __syncthreads();
    for (int st = 256; st > 0; st >>= 1) {
        if (threadIdx.x < st) { sh[threadIdx.x] += sh[threadIdx.x + st]; sh2[threadIdx.x] += sh2[threadIdx.x + st]; }
        __syncthreads();
    }
    if (threadIdx.x == 0) {
        float m = sh[0] / (float)NBL;
        float var = sh2[0] / (float)NBL - m * m;
        float cf = scale[c] * rsqrtf(var + EPSV);
        g_coeff[sel * CC + c] = cf;
        g_off[sel * CC + c]   = bias[c] - m * cf;
    }
}

__global__ void rope_kernel(const float* __restrict__ freqs) {
    int b  = blockIdx.z;
    int c0 = blockIdx.y * 64;
    int l0 = blockIdx.x * 32;
    __shared__ float s[64][33];
    for (int which = 0; which < 2; which++) {
        const float* src = which ? g_k : g_q;
        const float* cf  = g_coeff + which * CC;
        const float* of  = g_off   + which * CC;
        __nv_bfloat16* dh = which ? g_Kh : g_Qh;
        __nv_bfloat16* dl = which ? g_Kl : g_Ql;
        for (int t = threadIdx.x; t < 64 * 32; t += 256) {
            int cl = t / 32, ll = t - cl * 32;
            int c = c0 + cl, l = l0 + ll;
            float v = 0.f;
            if (l < LL) v = src[((size_t)b * CC + c) * LL + l] * cf[c] + of[c];
            s[cl][ll] = v;
        }
        __syncthreads();
        for (int t = threadIdx.x; t < 32 * 32; t += 256) {
            int ll = t / 32, dl2 = t - ll * 32;
            int l = l0 + ll;
            if (l < LL) {
                int d = c0 / 2 + dl2;
                float a  = s[2 * dl2][ll];
                float bb = s[2 * dl2 + 1][ll];
                float ra, rb;
                if (l == 0) { ra = a; rb = bb; }
                else {
                    float nf = (float)(l - 1);
                    float tx = fmodf(nf, 14.0f);
                    float ty = floorf(nf / 14.0f);
                    float ang = tx * freqs[d] + ty * freqs[384 + d];
                    float sn, cs;
                    sincosf(ang, &sn, &cs);
                    ra = a * cs - bb * sn;
                    rb = a * sn + bb * cs;
                }
                size_t o = ((size_t)b * LPAD + l) * CC + c0 + 2 * dl2;
                bf16split(ra, &dh[o], &dl[o]);
                bf16split(rb, &dh[o + 1], &dl[o + 1]);
            }
        }
        __syncthreads();
    }
}

__global__ void __launch_bounds__(256)
energy_mma() {
    extern __shared__ char smem[];
    uint32_t sb = s2u(smem);
    int tid = threadIdx.x, wid = tid >> 5, lane = tid & 31;
    int m0 = blockIdx.x * 128, n0 = blockIdx.y * 128, b = blockIdx.z;
    int wm = wid & 1, wn = wid >> 1;
    const __nv_bfloat16* Ah = g_Qh + (size_t)b * LPAD * CC;
    const __nv_bfloat16* Al = g_Ql + (size_t)b * LPAD * CC;
    const __nv_bfloat16* Bh = g_Kh + (size_t)b * LPAD * CC;
    const __nv_bfloat16* Bl = g_Kl + (size_t)b * LPAD * CC;

    float acc[4][4][4];
    #pragma unroll
    for (int mt = 0; mt < 4; mt++)
        #pragma unroll
        for (int nt = 0; nt < 4; nt++)
            #pragma unroll
            for (int e = 0; e < 4; e++) acc[mt][nt][e] = 0.f;

    auto load_chunk = [&](int c, int s) {
        int k0 = c * 32;
        uint32_t st = sb + s * TSTG;
        #pragma unroll
        for (int i = 0; i < 2; i++) {
            int idx = tid + 256 * i;
            int row = idx >> 2, sub = idx & 3;
            uint32_t so = (uint32_t)(row * RSTRIDE + sub * 16);
            CPA16(st + so,         Ah + (size_t)(m0 + row) * CC + k0 + sub * 8);
            CPA16(st + ABT + so,   Al + (size_t)(m0 + row) * CC + k0 + sub * 8);
            CPA16(st + 2*ABT + so, Bh + (size_t)(n0 + row) * CC + k0 + sub * 8);
            CPA16(st + 3*ABT + so, Bl + (size_t)(n0 + row) * CC + k0 + sub * 8);
        }
    };

    load_chunk(0, 0);
    asm volatile("cp.async.commit_group;" ::: "memory");
    load_chunk(1, 1);
    asm volatile("cp.async.commit_group;" ::: "memory");

    int g = lane >> 3, r = lane & 7;
    const int NCH = CC / 32;
    for (int c = 0; c < NCH; c++) {
        int s = c % 3;
        asm volatile("cp.async.wait_group 1;" ::: "memory");
        __syncthreads();
        uint32_t stg = sb + s * TSTG;
        #pragma unroll
        for (int ks = 0; ks < 2; ks++) {
            uint32_t ah[4][4], al[4][4];
            #pragma unroll
            for (int mt = 0; mt < 4; mt++) {
                uint32_t arow = (uint32_t)(wm * 64 + mt * 16 + r + (g & 1) * 8);
                uint32_t acol = (uint32_t)((2 * ks + (g >> 1)) * 16);
                ldsm4(ah[mt], stg + arow * RSTRIDE + acol);
                ldsm4(al[mt], stg + ABT + arow * RSTRIDE + acol);
            }
            #pragma unroll
            for (int np = 0; np < 2; np++) {
                uint32_t brow = (uint32_t)(wn * 32 + np * 16 + (g >> 1) * 8 + r);
                uint32_t bcol = (uint32_t)((2 * ks + (g & 1)) * 16);
                uint32_t bh[4], bl[4];
                ldsm4(bh, stg + 2*ABT + brow * RSTRIDE + bcol);
                ldsm4(bl, stg + 3*ABT + brow * RSTRIDE + bcol);
                #pragma unroll
                for (int mt = 0; mt < 4; mt++) {
                    mma16816(acc[mt][2 * np],     ah[mt], &bh[0]);
                    mma16816(acc[mt][2 * np + 1], ah[mt], &bh[2]);
                    mma16816(acc[mt][2 * np],     ah[mt], &bl[0]);
                    mma16816(acc[mt][2 * np + 1], ah[mt], &bl[2]);
                    mma16816(acc[mt][2 * np],     al[mt], &bh[0]);
                    mma16816(acc[mt][2 * np + 1], al[mt], &bh[2]);
                }
            }
        }
        if (c + 2 < NCH) load_chunk(c + 2, (c + 2) % 3);
        asm volatile("cp.async.commit_group;" ::: "memory");
    }

    int lrow = lane >> 2, lcol = (lane & 3) * 2;
    float* ab = g_att + (size_t)b * LL * LL;
    #pragma unroll
    for (int mt = 0; mt < 4; mt++)
        #pragma unroll
        for (int nt = 0; nt < 4; nt++)
            #pragma unroll
            for (int e = 0; e < 4; e++) {
                int i = m0 + wm * 64 + mt * 16 + lrow + (e >> 1) * 8;
                int j = n0 + wn * 32 + nt * 8 + lcol + (e & 1);
                if (i < LL && j < LL) ab[(size_t)i * LL + j] = acc[mt][nt][e];
            }
}

// ---- single-pass softmax: rows cached in registers, no write-back to g_att ----
__global__ void softmax_kernel() {
    int row = blockIdx.x * blockDim.y + threadIdx.y;
    if (row >= NBL) return;
    int b = row / LL, i = row - b * LL;
    const float* e = g_att + (size_t)row * LL;
    int lane = threadIdx.x;
    float vals[7];
    float mx = -1e30f;
    #pragma unroll
    for (int k = 0; k < 7; k++) {
        int j = lane + 32 * k;
        float v = (j < LL) ? e[j] : -1e30f;
        vals[k] = v;
        mx = fmaxf(mx, v);
    }
    #pragma unroll
    for (int o = 16; o; o >>= 1) mx = fmaxf(mx, __shfl_xor_sync(0xffffffffu, mx, o));
    float s = 0.f;
    #pragma unroll
    for (int k = 0; k < 7; k++) {
        int j = lane + 32 * k;
        float v = (j < LL) ? __expf(vals[k] - mx) : 0.f;
        vals[k] = v;
        s += v;
    }
    #pragma unroll
    for (int o = 16; o; o >>= 1) s += __shfl_xor_sync(0xffffffffu, s, o);
    float inv = 1.f / s;
    __nv_bfloat16* ah = g_atth + ((size_t)b * LPAD + i) * JPAD;
    __nv_bfloat16* al = g_attl + ((size_t)b * LPAD + i) * JPAD;
    #pragma unroll
    for (int k = 0; k < 7; k++) {
        int j = lane + 32 * k;
        float v = (j < LL) ? vals[k] * inv : 0.f;
        bf16split(v, &ah[j], &al[j]);
    }
}

__global__ void vconv() {
    for (int idx = blockIdx.x * blockDim.x + threadIdx.x;
         idx < BB * CC * JPAD; idx += gridDim.x * blockDim.x) {
        int j = idx % JPAD;
        int bc = idx / JPAD;
        int c = bc % CC, b = bc / CC;
        float v = 0.f;
        if (j < LL)
            v = g_v[((size_t)b * CC + c) * LL + j] * g_coeff[2 * CC + c] + g_off[2 * CC + c];
        bf16split(v, &g_vh[idx], &g_vl[idx]);
    }
}

__global__ void __launch_bounds__(256)
out_mma(const float* __restrict__ x, const float* __restrict__ gamma) {
    extern __shared__ char smem[];
    uint32_t sb = s2u(smem);
    int tid = threadIdx.x, wid = tid >> 5, lane = tid & 31;
    int m0 = blockIdx.x * 128, n0 = blockIdx.y * 128, b = blockIdx.z;
    int wm = wid & 1, wn = wid >> 1;
    const __nv_bfloat16* Ah = g_vh + (size_t)b * CC * JPAD;
    const __nv_bfloat16* Al = g_vl + (size_t)b * CC * JPAD;
    const __nv_bfloat16* Bh = g_atth + (size_t)b * LPAD * JPAD;
    const __nv_bfloat16* Bl = g_attl + (size_t)b * LPAD * JPAD;

    float acc[4][4][4];
    #pragma unroll
    for (int mt = 0; mt < 4; mt++)
        #pragma unroll
        for (int nt = 0; nt < 4; nt++)
            #pragma unroll
            for (int e = 0; e < 4; e++) acc[mt][nt][e] = 0.f;

    auto load_chunk = [&](int c, int s) {
        int k0 = c * 32;
        uint32_t st = sb + s * TSTG;
        #pragma unroll
        for (int i = 0; i < 2; i++) {
            int idx = tid + 256 * i;
            int row = idx >> 2, sub = idx & 3;
            uint32_t so = (uint32_t)(row * RSTRIDE + sub * 16);
            CPA16(st + so,         Ah + (size_t)(m0 + row) * JPAD + k0 + sub * 8);
            CPA16(st + ABT + so,   Al + (size_t)(m0 + row) * JPAD + k0 + sub * 8);
            CPA16(st + 2*ABT + so, Bh + (size_t)(n0 + row) * JPAD + k0 + sub * 8);
            CPA16(st + 3*ABT + so, Bl + (size_t)(n0 + row) * JPAD + k0 + sub * 8);
        }
    };

    load_chunk(0, 0);
    asm volatile("cp.async.commit_group;" ::: "memory");
    load_chunk(1, 1);
    asm volatile("cp.async.commit_group;" ::: "memory");

    int g = lane >> 3, r = lane & 7;
    const int NCH = JPAD / 32;
    for (int c = 0; c < NCH; c++) {
        int s = c % 3;
        asm volatile("cp.async.wait_group 1;" ::: "memory");
        __syncthreads();
        uint32_t stg = sb + s * TSTG;
        #pragma unroll
        for (int ks = 0; ks < 2; ks++) {
            uint32_t ah[4][4], al[4][4];
            #pragma unroll
            for (int mt = 0; mt < 4; mt++) {
                uint32_t arow = (uint32_t)(wm * 64 + mt * 16 + r + (g & 1) * 8);
                uint32_t acol = (uint32_t)((2 * ks + (g >> 1)) * 16);
                ldsm4(ah[mt], stg + arow * RSTRIDE + acol);
                ldsm4(al[mt], stg + ABT + arow * RSTRIDE + acol);
            }
            #pragma unroll
            for (int np = 0; np < 2; np++) {
                uint32_t brow = (uint32_t)(wn * 32 + np * 16 + (g >> 1) * 8 + r);
                uint32_t bcol = (uint32_t)((2 * ks + (g & 1)) * 16);
                uint32_t bh[4], bl[4];
                ldsm4(bh, stg + 2*ABT + brow * RSTRIDE + bcol);
                ldsm4(bl, stg + 3*ABT + brow * RSTRIDE + bcol);
                #pragma unroll
                for (int mt = 0; mt < 4; mt++) {
                    mma16816(acc[mt][2 * np],     ah[mt], &bh[0]);
                    mma16816(acc[mt][2 * np + 1], ah[mt], &bh[2]);
                    mma16816(acc[mt][2 * np],     ah[mt], &bl[0]);
                    mma16816(acc[mt][2 * np + 1], ah[mt], &bl[2]);
                    mma16816(acc[mt][2 * np],     al[mt], &bh[0]);
                    mma16816(acc[mt][2 * np + 1], al[mt], &bh[2]);
                }
            }
        }
        if (c + 2 < NCH) load_chunk(c + 2, (c + 2) % 3);
        asm volatile("cp.async.commit_group;" ::: "memory");
    }

    float g0 = gamma[0];
    int lrow = lane >> 2, lcol = (lane & 3) * 2;
    #pragma unroll
    for (int mt = 0; mt < 4; mt++)
        #pragma unroll
        for (int nt = 0; nt < 4; nt++)
            #pragma unroll
            for (int e = 0; e < 4; e++) {
                int cch = m0 + wm * 64 + mt * 16 + lrow + (e >> 1) * 8;
                int i = n0 + wn * 32 + nt * 8 + lcol + (e & 1);
                if (i < LL) {
                    size_t o = ((size_t)b * CC + cch) * LL + i;
                    g_y[o] = g0 * x[o] + acc[mt][nt][e];
                }
            }
}

__global__ void final_norm(float* __restrict__ out) {
    int base = (blockIdx.x * blockDim.x + threadIdx.x) * 2;
    #pragma unroll
    for (int u = 0; u < 2; u++) {
        int idx = base + u;
        if (idx < BB * CC * LL) {
            int c = (idx / LL) % CC;
            out[idx] = g_y[idx] * g_coeff[3 * CC + c] + g_off[3 * CC + c];
        }
    }
}

extern "C" void kernel_launch(void* const* d_in, const int* in_sizes, int n_in,
                              void* d_out, int out_size) {
    const float* x      = (const float*)d_in[0];
    const float* Wq     = (const float*)d_in[1];
    const float* Wk     = (const float*)d_in[2];
    const float* Wv     = (const float*)d_in[3];
    const float* bnq_s  = (const float*)d_in[4];
    const float* bnq_b  = (const float*)d_in[5];
    const float* bnk_s  = (const float*)d_in[6];
    const float* bnk_b  = (const float*)d_in[7];
    const float* bnv_s  = (const float*)d_in[8];
    const float* bnv_b  = (const float*)d_in[9];
    const float* gamma  = (const float*)d_in[10];
    const float* freqs  = (const float*)d_in[11];
    const float* norm_s = (const float*)d_in[12];
    const float* norm_b = (const float*)d_in[13];
    float* out = (float*)d_out;

    cudaFuncSetAttribute(conv_mma, cudaFuncAttributeMaxDynamicSharedMemorySize, SMEMSZ);
    cudaFuncSetAttribute(energy_mma, cudaFuncAttributeMaxDynamicSharedMemorySize, TSMEM);
    cudaFuncSetAttribute(out_mma, cudaFuncAttributeMaxDynamicSharedMemorySize, TSMEM);

    build_zT<<<(ZT_MAIN + ZT_PADS + 255) / 256, 256>>>(x);
    build_W_all<<<(MDIM * KDIM + 255) / 256, 256>>>(Wq, Wk, Wv);
    build_bias<<<MDIM, 96>>>(Wq, Wk, Wv);
    conv_mma<<<dim3(MDIM / 128, NP / 256), 512, SMEMSZ>>>();
    bn_stats3<<<dim3(CC, 3), 512>>>(bnq_s, bnq_b, bnk_s, bnk_b, bnv_s, bnv_b);
    rope_kernel<<<dim3(7, 12, BB), 256>>>(freqs);
    vconv<<<1184, 256>>>();
    energy_mma<<<dim3(2, 2, BB), 256, TSMEM>>>();
    softmax_kernel<<<dim3((NBL + 7) / 8), dim3(32, 8)>>>();
    out_mma<<<dim3(CC / 128, 2, BB), 256, TSMEM>>>(x, gamma);
    bn_stats<<<CC, 512>>>(3, norm_s, norm_b);
    final_norm<<<(BB * CC * LL / 2 + 255) / 256, 256>>>(out);
}